// round 12
// baseline (speedup 1.0000x reference)
#include <cuda_runtime.h>
#include <math.h>
#include <stdint.h>

// Problem constants (fixed shapes for GCM_60490319396973)
constexpr int N_   = 40000;
constexpr int DIM_ = 256;
constexpr int H_   = 128;
constexpr int K_   = 27;
constexpr int B_   = 4;
constexpr int KH_  = K_ * H_;      // 3456
constexpr int NPART = 250;
constexpr int CHUNK = (N_ + NPART - 1) / NPART;   // 160

// ---------------- scratch (device globals: no allocation allowed) ----------
__device__ float g_convx[(N_ + 1) * H_];   // padded: row N_ is the zero row
__device__ float g_glo  [(N_ + 1) * H_];
__device__ float g_r1   [(N_ + 1) * H_];
__device__ float g_convout[N_ * H_];
__device__ float g_f1[N_ * H_];
__device__ float g_f2[N_ * H_];
__device__ float g_t [N_ * H_];
__device__ float g_part[NPART * B_ * H_];
__device__ int   g_cnt [NPART * B_];
__device__ float g_m2  [B_ * H_];
// tf32-pre-rounded operands
__device__ float g_xr  [N_ * DIM_];
__device__ float g_W1r [DIM_ * DIM_];
__device__ float g_W2r [DIM_ * DIM_];
__device__ float g_Wg3r[H_ * H_];
// column-PERMUTED + rounded sconv weights (fragment-order columns)
__device__ float g_Wr1p[KH_ * H_];
__device__ float g_Wr2p[KH_ * H_];
__device__ float g_Wg1p[KH_ * H_];
__device__ float g_Wg2p[KH_ * H_];

// ---------------- helpers ----------------------------------------------------
__device__ __forceinline__ uint32_t f2tf32(float x) {
    uint32_t y;
    asm("cvt.rna.tf32.f32 %0, %1;" : "=r"(y) : "f"(x));
    return y;
}
__device__ __forceinline__ float rnd_tf32(float x) {
    return __uint_as_float(f2tf32(x));
}
__device__ __forceinline__ void mma_tf32(float c[4], const uint32_t a[4],
                                         const uint32_t b[2]) {
    asm volatile(
        "mma.sync.aligned.m16n8k8.row.col.f32.tf32.tf32.f32 "
        "{%0,%1,%2,%3}, {%4,%5,%6,%7}, {%8,%9}, {%0,%1,%2,%3};\n"
        : "+f"(c[0]), "+f"(c[1]), "+f"(c[2]), "+f"(c[3])
        : "r"(a[0]), "r"(a[1]), "r"(a[2]), "r"(a[3]), "r"(b[0]), "r"(b[1]));
}
__device__ __forceinline__ void cp16(uint32_t dst, const void* src, bool valid) {
    asm volatile("cp.async.cg.shared.global [%0], [%1], 16, %2;"
                 :: "r"(dst), "l"(src), "r"(valid ? 16 : 0));
}
__device__ __forceinline__ void cp16g(uint32_t dst, const void* src) {
    asm volatile("cp.async.cg.shared.global [%0], [%1], 16;"
                 :: "r"(dst), "l"(src));
}
__device__ __forceinline__ void cp_commit() {
    asm volatile("cp.async.commit_group;");
}
__device__ __forceinline__ void cp_wait0() {
    asm volatile("cp.async.wait_group 0;");
}

// ---------------- tiny kernels ---------------------------------------------
__global__ void zero_pad_kernel() {
    int t = threadIdx.x;                 // 128 threads
    g_convx[N_ * H_ + t] = 0.f;
    g_glo  [N_ * H_ + t] = 0.f;
    g_r1   [N_ * H_ + t] = 0.f;
}

__global__ void round_copy_kernel(const float* __restrict__ src,
                                  float* __restrict__ dst, int n4) {
    int i = blockIdx.x * blockDim.x + threadIdx.x;
    if (i >= n4) return;
    float4 v = reinterpret_cast<const float4*>(src)[i];
    v.x = rnd_tf32(v.x); v.y = rnd_tf32(v.y);
    v.z = rnd_tf32(v.z); v.w = rnd_tf32(v.w);
    reinterpret_cast<float4*>(dst)[i] = v;
}

// round + permute columns into mma-fragment order:
// store_idx(n) = (n&7)*16 + (n>>6)*8 + ((n>>3)&7)
__global__ void round_permute_kernel(const float* __restrict__ src,
                                     float* __restrict__ dst) {
    int i = blockIdx.x * blockDim.x + threadIdx.x;   // over KH_ * H_
    if (i >= KH_ * H_) return;
    int k = i >> 7, n = i & 127;
    int p = ((n & 7) << 4) | ((n >> 6) << 3) | ((n >> 3) & 7);
    dst[(k << 7) + p] = rnd_tf32(src[i]);
}

// ---------------- sconv: tf32 HMMA, permuted-B LDS.128 fragments ------------
// C[m, 0:128] = epi( bias + sum_{k,c} A[nbr[m,k], c] * W[k*128+c, :] )
enum { EPI_RELU = 0, EPI_R2 = 1 };

constexpr int STILE = 128;
constexpr int SBK   = 32;
constexpr int SPA   = SBK + 4;          // 36
constexpr int SPB   = STILE + 4;        // 132: conflict-free LDS.128 frag reads
constexpr int SNT   = KH_ / SBK;        // 108
constexpr int SCONV_SMEM = (2 * STILE * SPA + 2 * SBK * SPB + STILE * K_) * 4;

template <int EPI, int RND>
__global__ void __launch_bounds__(256, 2)
sconv_kernel(const float* __restrict__ A,   // (N_+1) x 128, rounded, zero row N_
             const int* __restrict__ nbr,
             const float* __restrict__ Bm,  // [3456][128] col-PERMUTED, rounded
             const float* __restrict__ bias,
             const float* __restrict__ aux,
             float* __restrict__ C)
{
    extern __shared__ char smem_raw[];
    float* As   = reinterpret_cast<float*>(smem_raw);        // [2][128][SPA]
    float* Bs   = As + 2 * STILE * SPA;                      // [2][32][SPB]
    int*   snbr = reinterpret_cast<int*>(Bs + 2 * SBK * SPB);// [128][27]

    const int tid  = threadIdx.x;
    const int m0   = blockIdx.x * STILE;
    const int lane = tid & 31;
    const int wid  = tid >> 5;         // 0..7
    const int wm   = wid & 3;          // warp row (4 x 32 = 128)
    const int wn   = wid >> 2;         // warp col (2 x 64 = 128)
    const int g    = lane >> 2;        // 0..7
    const int tg   = lane & 3;         // 0..3

    for (int i = tid; i < STILE * K_; i += 256) {
        int r = i / K_, k = i % K_;
        int row = m0 + r;
        snbr[i] = (row < N_) ? nbr[row * K_ + k] : N_;   // N_ -> zero row
    }
    __syncthreads();

    auto stage = [&](int t, int buf) {
        int k0 = t * SBK;
        int kidx = k0 >> 7;
        int csub = k0 & 127;
        float* Ab = As + buf * STILE * SPA;
        float* Bb = Bs + buf * SBK * SPB;
#pragma unroll
        for (int it = 0; it < 4; it++) {
            int idx = tid + it * 256;
            int r   = idx >> 3;            // 0..127
            int c4  = (idx & 7) << 2;      // 0..28
            uint32_t dst = (uint32_t)__cvta_generic_to_shared(&Ab[r * SPA + c4]);
            int src = snbr[r * K_ + kidx];
            cp16g(dst, A + (size_t)src * H_ + csub + c4);
        }
#pragma unroll
        for (int it = 0; it < 4; it++) {
            int idx = tid + it * 256;
            int r   = idx >> 5;            // 0..31
            int cc  = (idx & 31) << 2;     // 0..124
            uint32_t dst = (uint32_t)__cvta_generic_to_shared(&Bb[r * SPB + cc]);
            cp16g(dst, Bm + (size_t)(k0 + r) * H_ + cc);
        }
    };

    float acc[2][8][4];
#pragma unroll
    for (int mt = 0; mt < 2; mt++)
#pragma unroll
        for (int nt = 0; nt < 8; nt++)
#pragma unroll
            for (int j = 0; j < 4; j++) acc[mt][nt][j] = 0.f;

    stage(0, 0);
    cp_commit();

    int buf = 0;
    for (int t = 0; t < SNT; t++) {
        cp_wait0();
        __syncthreads();
        if (t + 1 < SNT) { stage(t + 1, buf ^ 1); cp_commit(); }

        const uint32_t* Ab =
            reinterpret_cast<const uint32_t*>(As + buf * STILE * SPA);
        const uint32_t* Bb =
            reinterpret_cast<const uint32_t*>(Bs + buf * SBK * SPB);
#pragma unroll
        for (int ks = 0; ks < SBK; ks += 8) {
            // B fragments: permuted columns -> 8 consecutive floats per row
            const uint32_t* r0 = Bb + (ks + tg)     * SPB + g * 16 + wn * 8;
            const uint32_t* r1 = Bb + (ks + tg + 4) * SPB + g * 16 + wn * 8;
            uint4 b00 = *reinterpret_cast<const uint4*>(r0);
            uint4 b01 = *reinterpret_cast<const uint4*>(r0 + 4);
            uint4 b10 = *reinterpret_cast<const uint4*>(r1);
            uint4 b11 = *reinterpret_cast<const uint4*>(r1 + 4);
            uint32_t bfr[8][2] = {
                {b00.x, b10.x}, {b00.y, b10.y}, {b00.z, b10.z}, {b00.w, b10.w},
                {b01.x, b11.x}, {b01.y, b11.y}, {b01.z, b11.z}, {b01.w, b11.w}};
#pragma unroll
            for (int mt = 0; mt < 2; mt++) {
                int m = wm * 32 + mt * 16 + g;
                uint32_t af[4];
                af[0] = Ab[m       * SPA + ks + tg];
                af[1] = Ab[(m + 8) * SPA + ks + tg];
                af[2] = Ab[m       * SPA + ks + tg + 4];
                af[3] = Ab[(m + 8) * SPA + ks + tg + 4];
#pragma unroll
                for (int nt = 0; nt < 8; nt++)
                    mma_tf32(acc[mt][nt], af, bfr[nt]);
            }
        }
        buf ^= 1;
    }

    // ---- epilogue (logical column mapping unchanged by the B permutation) ----
#pragma unroll
    for (int mt = 0; mt < 2; mt++) {
#pragma unroll
        for (int half = 0; half < 2; half++) {
            int row = m0 + wm * 32 + mt * 16 + g + half * 8;
            if (row >= N_) continue;
#pragma unroll
            for (int nt = 0; nt < 8; nt++) {
                int col = wn * 64 + nt * 8 + tg * 2;
                float v0 = acc[mt][nt][half * 2 + 0] + bias[col];
                float v1 = acc[mt][nt][half * 2 + 1] + bias[col + 1];
                float o0, o1;
                if (EPI == EPI_RELU) {
                    o0 = fmaxf(v0, 0.f);
                    o1 = fmaxf(v1, 0.f);
                } else {  // EPI_R2
                    float2 a = *reinterpret_cast<const float2*>(
                        aux + (size_t)row * H_ + col);
                    o0 = fmaxf(v0, 0.f) + 2.f * a.x;
                    o1 = fmaxf(v1, 0.f) + 2.f * a.y;
                }
                if (RND) { o0 = rnd_tf32(o0); o1 = rnd_tf32(o1); }
                *reinterpret_cast<float2*>(C + (size_t)row * H_ + col) =
                    make_float2(o0, o1);
            }
        }
    }
}

// ---------------- legacy tf32 HMMA GEMM (dense / concat paths) ---------------
enum { AM_DENSE = 0, AM_CONCAT = 2 };
enum { EP_SPLIT = 0, EP_GLO = 3, EP_FINAL = 4 };

constexpr int TILE = 128;
constexpr int BK   = 32;
constexpr int PA   = BK + 4;
constexpr int PB   = TILE + 8;
constexpr int SMEM_BYTES = 2 * TILE * PA * 4 + 2 * BK * PB * 4;

template <int AMODE, int EPI, int RND>
__global__ void __launch_bounds__(256, 2)
gemm_kernel(const float* __restrict__ A, const float* __restrict__ A2,
            const float* __restrict__ Bm, int ldb, int Kdim, int lda,
            const float* __restrict__ bias,
            const float* __restrict__ aux,
            float* __restrict__ C, float* __restrict__ C2)
{
    extern __shared__ char smem_raw[];
    float* As = reinterpret_cast<float*>(smem_raw);          // [2][128][PA]
    float* Bs = As + 2 * TILE * PA;                          // [2][32][PB]

    const int tid = threadIdx.x;
    const int m0  = blockIdx.x * TILE;
    const int n0  = blockIdx.y * TILE;

    const int lane = tid & 31;
    const int wid  = tid >> 5;
    const int wm   = wid & 3;
    const int wn   = wid >> 2;
    const int g    = lane >> 2;
    const int tg   = lane & 3;

    auto stage = [&](int k0, int buf) {
        float* Ab = As + buf * TILE * PA;
        float* Bb = Bs + buf * BK * PB;
#pragma unroll
        for (int it = 0; it < 4; it++) {
            int idx = tid + it * 256;
            int r   = idx >> 3;
            int c4  = (idx & 7) << 2;
            uint32_t dst = (uint32_t)__cvta_generic_to_shared(&Ab[r * PA + c4]);
            if (AMODE == AM_DENSE) {
                int row = m0 + r;
                cp16(dst, A + (size_t)row * lda + k0 + c4, row < N_);
            } else {  // AM_CONCAT
                int row = m0 + r;
                int gc  = k0 + c4;
                const float* srcp = (gc < H_) ? A : A2;
                int cc = (gc < H_) ? gc : gc - H_;
                cp16(dst, srcp + (size_t)row * H_ + cc, row < N_);
            }
        }
#pragma unroll
        for (int it = 0; it < 4; it++) {
            int idx = tid + it * 256;
            int r   = idx >> 5;
            int c4  = (idx & 31) << 2;
            uint32_t dst = (uint32_t)__cvta_generic_to_shared(&Bb[r * PB + c4]);
            cp16(dst, Bm + (size_t)(k0 + r) * ldb + n0 + c4, true);
        }
    };

    float acc[2][8][4];
#pragma unroll
    for (int mt = 0; mt < 2; mt++)
#pragma unroll
        for (int nt = 0; nt < 8; nt++)
#pragma unroll
            for (int j = 0; j < 4; j++) acc[mt][nt][j] = 0.f;

    const int niter = Kdim / BK;
    stage(0, 0);
    cp_commit();

    int buf = 0;
    for (int i = 0; i < niter; i++) {
        cp_wait0();
        __syncthreads();
        if (i + 1 < niter) { stage((i + 1) * BK, buf ^ 1); cp_commit(); }

        const uint32_t* Ab =
            reinterpret_cast<const uint32_t*>(As + buf * TILE * PA);
        const uint32_t* Bb =
            reinterpret_cast<const uint32_t*>(Bs + buf * BK * PB);
#pragma unroll
        for (int ks = 0; ks < BK; ks += 8) {
            uint32_t bfr[8][2];
#pragma unroll
            for (int nt = 0; nt < 8; nt++) {
                int n = wn * 64 + nt * 8 + g;
                bfr[nt][0] = Bb[(ks + tg)     * PB + n];
                bfr[nt][1] = Bb[(ks + tg + 4) * PB + n];
            }
#pragma unroll
            for (int mt = 0; mt < 2; mt++) {
                int m = wm * 32 + mt * 16 + g;
                uint32_t af[4];
                af[0] = Ab[m       * PA + ks + tg];
                af[1] = Ab[(m + 8) * PA + ks + tg];
                af[2] = Ab[m       * PA + ks + tg + 4];
                af[3] = Ab[(m + 8) * PA + ks + tg + 4];
#pragma unroll
                for (int nt = 0; nt < 8; nt++)
                    mma_tf32(acc[mt][nt], af, bfr[nt]);
            }
        }
        buf ^= 1;
    }

#pragma unroll
    for (int mt = 0; mt < 2; mt++) {
#pragma unroll
        for (int half = 0; half < 2; half++) {
            int row = m0 + wm * 32 + mt * 16 + g + half * 8;
            if (row >= N_) continue;
#pragma unroll
            for (int nt = 0; nt < 8; nt++) {
                int col = n0 + wn * 64 + nt * 8 + tg * 2;
                float v0 = acc[mt][nt][half * 2 + 0] + bias[col];
                float v1 = acc[mt][nt][half * 2 + 1] + bias[col + 1];
                if (EPI == EP_SPLIT) {
                    float o0 = RND ? rnd_tf32(v0) : v0;
                    float o1 = RND ? rnd_tf32(v1) : v1;
                    if (col < H_) {
                        C [(size_t)row * H_ + col]     = o0;
                        C [(size_t)row * H_ + col + 1] = o1;
                    } else {
                        C2[(size_t)row * H_ + col - H_]     = o0;
                        C2[(size_t)row * H_ + col - H_ + 1] = o1;
                    }
                } else if (EPI == EP_GLO) {
                    float2 a = *reinterpret_cast<const float2*>(
                        aux + (size_t)row * H_ + col);
                    float o0 = fmaxf(a.x - fmaxf(v0, 0.f), 0.f);
                    float o1 = fmaxf(a.y - fmaxf(v1, 0.f), 0.f);
                    if (RND) { o0 = rnd_tf32(o0); o1 = rnd_tf32(o1); }
                    *reinterpret_cast<float2*>(C + (size_t)row * H_ + col) =
                        make_float2(o0, o1);
                } else {  // EP_FINAL
                    float2 a = *reinterpret_cast<const float2*>(
                        aux + (size_t)row * DIM_ + col);
                    *reinterpret_cast<float2*>(C + (size_t)row * DIM_ + col) =
                        make_float2(a.x + v0, a.y + v1);
                }
            }
        }
    }
}

// ---------------- deterministic segment mean (m2) ---------------------------
__global__ void seg_partial_kernel(const int* __restrict__ bids) {
    int blk = blockIdx.x;
    int o   = threadIdx.x;
    int r0  = blk * CHUNK;
    int r1  = min(r0 + CHUNK, N_);
    float a0 = 0.f, a1 = 0.f, a2 = 0.f, a3 = 0.f;
    for (int r = r0; r < r1; r++) {
        int   b = bids[r];
        float v = g_f2[(size_t)r * H_ + o];
        a0 += (b == 0) ? v : 0.f;
        a1 += (b == 1) ? v : 0.f;
        a2 += (b == 2) ? v : 0.f;
        a3 += (b == 3) ? v : 0.f;
    }
    g_part[(blk * B_ + 0) * H_ + o] = a0;
    g_part[(blk * B_ + 1) * H_ + o] = a1;
    g_part[(blk * B_ + 2) * H_ + o] = a2;
    g_part[(blk * B_ + 3) * H_ + o] = a3;
    if (o < B_) {
        int c = 0;
        for (int r = r0; r < r1; r++) c += (bids[r] == o);
        g_cnt[blk * B_ + o] = c;
    }
}

__global__ void seg_final_kernel() {
    int t = threadIdx.x;
    float s = 0.f;
    for (int p = 0; p < NPART; p++) s += g_part[p * B_ * H_ + t];
    __shared__ int scnt[B_];
    if (t < B_) {
        int c = 0;
        for (int p = 0; p < NPART; p++) c += g_cnt[p * B_ + t];
        scnt[t] = c;
    }
    __syncthreads();
    int b = t / H_;
    float cnt = (float)max(scnt[b], 1);
    g_m2[t] = s / cnt;
}

// ---------------- enc / t = enc + f1 + f2 (stores tf32-rounded) -------------
__global__ void enc_kernel(const int* __restrict__ bids) {
    int warp = threadIdx.x >> 5;
    int lane = threadIdx.x & 31;
    int row  = blockIdx.x * 4 + warp;

    float4 f1v = reinterpret_cast<const float4*>(g_f1 + (size_t)row * H_)[lane];
    float s = f1v.x + f1v.y + f1v.z + f1v.w;
#pragma unroll
    for (int off = 16; off; off >>= 1) s += __shfl_xor_sync(0xffffffffu, s, off);
    float row1 = s * (1.f / 128.f);

    int b = bids[row];
    float4 f2v = reinterpret_cast<const float4*>(g_f2 + (size_t)row * H_)[lane];
    float4 m2v = reinterpret_cast<const float4*>(g_m2 + b * H_)[lane];

    float4 t;
    t.x = rnd_tf32(sqrtf(row1 * m2v.x + 1e-12f) + f1v.x + f2v.x);
    t.y = rnd_tf32(sqrtf(row1 * m2v.y + 1e-12f) + f1v.y + f2v.y);
    t.z = rnd_tf32(sqrtf(row1 * m2v.z + 1e-12f) + f1v.z + f2v.z);
    t.w = rnd_tf32(sqrtf(row1 * m2v.w + 1e-12f) + f1v.w + f2v.w);
    reinterpret_cast<float4*>(g_t + (size_t)row * H_)[lane] = t;
}

// ---------------- launch ----------------------------------------------------
static inline void round_copy(const float* src, float* dst, int n) {
    int n4 = n / 4;
    round_copy_kernel<<<(n4 + 255) / 256, 256>>>(src, dst, n4);
}

extern "C" void kernel_launch(void* const* d_in, const int* in_sizes, int n_in,
                              void* d_out, int out_size)
{
    const float* x    = (const float*)d_in[0];
    const int*   nbr  = (const int*)  d_in[1];
    const int*   bids = (const int*)  d_in[2];
    const float* W1   = (const float*)d_in[3];
    const float* b1   = (const float*)d_in[4];
    const float* W2   = (const float*)d_in[5];
    const float* b2   = (const float*)d_in[6];
    const float* Wr1  = (const float*)d_in[7];
    const float* br1  = (const float*)d_in[8];
    const float* Wr2  = (const float*)d_in[9];
    const float* br2  = (const float*)d_in[10];
    const float* Wg1  = (const float*)d_in[11];
    const float* bg1  = (const float*)d_in[12];
    const float* Wg2  = (const float*)d_in[13];
    const float* bg2  = (const float*)d_in[14];
    const float* Wg3  = (const float*)d_in[15];
    const float* bg3  = (const float*)d_in[16];
    float* out = (float*)d_out;

    float *convx, *glo, *r1, *convout, *f1, *f2, *tb;
    float *xr, *W1r, *W2r, *Wg3r, *Wr1p, *Wr2p, *Wg1p, *Wg2p;
    cudaGetSymbolAddress((void**)&convx,   g_convx);
    cudaGetSymbolAddress((void**)&glo,     g_glo);
    cudaGetSymbolAddress((void**)&r1,      g_r1);
    cudaGetSymbolAddress((void**)&convout, g_convout);
    cudaGetSymbolAddress((void**)&f1,      g_f1);
    cudaGetSymbolAddress((void**)&f2,      g_f2);
    cudaGetSymbolAddress((void**)&tb,      g_t);
    cudaGetSymbolAddress((void**)&xr,      g_xr);
    cudaGetSymbolAddress((void**)&W1r,     g_W1r);
    cudaGetSymbolAddress((void**)&W2r,     g_W2r);
    cudaGetSymbolAddress((void**)&Wg3r,    g_Wg3r);
    cudaGetSymbolAddress((void**)&Wr1p,    g_Wr1p);
    cudaGetSymbolAddress((void**)&Wr2p,    g_Wr2p);
    cudaGetSymbolAddress((void**)&Wg1p,    g_Wg1p);
    cudaGetSymbolAddress((void**)&Wg2p,    g_Wg2p);

    cudaFuncSetAttribute(gemm_kernel<AM_DENSE,  EP_SPLIT, 1>,
                         cudaFuncAttributeMaxDynamicSharedMemorySize, SMEM_BYTES);
    cudaFuncSetAttribute(gemm_kernel<AM_DENSE,  EP_GLO,   1>,
                         cudaFuncAttributeMaxDynamicSharedMemorySize, SMEM_BYTES);
    cudaFuncSetAttribute(gemm_kernel<AM_CONCAT, EP_FINAL, 0>,
                         cudaFuncAttributeMaxDynamicSharedMemorySize, SMEM_BYTES);
    cudaFuncSetAttribute(sconv_kernel<EPI_RELU, 1>,
                         cudaFuncAttributeMaxDynamicSharedMemorySize, SCONV_SMEM);
    cudaFuncSetAttribute(sconv_kernel<EPI_RELU, 0>,
                         cudaFuncAttributeMaxDynamicSharedMemorySize, SCONV_SMEM);
    cudaFuncSetAttribute(sconv_kernel<EPI_R2,   1>,
                         cudaFuncAttributeMaxDynamicSharedMemorySize, SCONV_SMEM);

    const int mt = (N_ + TILE - 1) / TILE;   // 313
    dim3 blk(256);
    const int pgrid = (KH_ * H_ + 255) / 256;

    // ---- prep: round static operands; permute sconv weight columns ----
    round_copy(x,   xr,   N_ * DIM_);
    round_copy(W1,  W1r,  DIM_ * DIM_);
    round_copy(W2,  W2r,  DIM_ * DIM_);
    round_copy(Wg3, Wg3r, H_ * H_);
    round_permute_kernel<<<pgrid, 256>>>(Wr1, Wr1p);
    round_permute_kernel<<<pgrid, 256>>>(Wr2, Wr2p);
    round_permute_kernel<<<pgrid, 256>>>(Wg1, Wg1p);
    round_permute_kernel<<<pgrid, 256>>>(Wg2, Wg2p);
    zero_pad_kernel<<<1, 128>>>();

    // h = x@W1 + b1 ; conv_x = h[:, :128] ; glo = h[:, 128:]  (stored rounded)
    gemm_kernel<AM_DENSE, EP_SPLIT, 1><<<dim3(mt, 2), blk, SMEM_BYTES>>>(
        xr, nullptr, W1r, DIM_, DIM_, DIM_, b1, nullptr, convx, glo);

    // sconvs: permuted-B HMMA kernels
    sconv_kernel<EPI_RELU, 1><<<mt, blk, SCONV_SMEM>>>(
        convx, nbr, Wr1p, br1, nullptr, r1);
    sconv_kernel<EPI_R2, 1><<<mt, blk, SCONV_SMEM>>>(
        r1, nbr, Wr2p, br2, convx, convout);
    sconv_kernel<EPI_RELU, 0><<<mt, blk, SCONV_SMEM>>>(
        glo, nbr, Wg1p, bg1, nullptr, f1);
    sconv_kernel<EPI_RELU, 0><<<mt, blk, SCONV_SMEM>>>(
        glo, nbr, Wg2p, bg2, nullptr, f2);

    // m2 = segment_mean(f2) (deterministic two-pass)
    seg_partial_kernel<<<NPART, 128>>>(bids);
    seg_final_kernel<<<1, 512>>>();

    // t = sqrt(mean(f1)*m2[bid] + 1e-12) + f1 + f2   (stored rounded)
    enc_kernel<<<N_ / 4, 128>>>(bids);

    // glo = relu(glo - relu(t@Wg3 + bg3))   (stored rounded)
    gemm_kernel<AM_DENSE, EP_GLO, 1><<<dim3(mt, 1), blk, SMEM_BYTES>>>(
        tb, nullptr, Wg3r, H_, H_, H_, bg3, glo, glo, nullptr);

    // out = x + [convout | glo] @ W2 + b2
    gemm_kernel<AM_CONCAT, EP_FINAL, 0><<<dim3(mt, 2), blk, SMEM_BYTES>>>(
        convout, glo, W2r, DIM_, DIM_, 0, b2, x, out, nullptr);
}

// round 13
// speedup vs baseline: 1.1036x; 1.1036x over previous
#include <cuda_runtime.h>
#include <math.h>
#include <stdint.h>

// Problem constants (fixed shapes for GCM_60490319396973)
constexpr int N_   = 40000;
constexpr int DIM_ = 256;
constexpr int H_   = 128;
constexpr int K_   = 27;
constexpr int B_   = 4;
constexpr int KH_  = K_ * H_;      // 3456
constexpr int NPART = 250;
constexpr int CHUNK = (N_ + NPART - 1) / NPART;   // 160

// ---------------- scratch (device globals: no allocation allowed) ----------
__device__ float g_convx[(N_ + 1) * H_];   // padded: row N_ is the zero row
__device__ float g_glo  [(N_ + 1) * H_];
__device__ float g_r1   [(N_ + 1) * H_];
__device__ float g_convout[N_ * H_];
__device__ float g_f1[N_ * H_];
__device__ float g_f2[N_ * H_];
__device__ float g_t [N_ * H_];
__device__ float g_part[NPART * B_ * H_];
__device__ int   g_cnt [NPART * B_];
__device__ float g_m2  [B_ * H_];
// tf32-pre-rounded operands
__device__ float g_xr  [N_ * DIM_];
__device__ float g_W1r [DIM_ * DIM_];
__device__ float g_W2r [DIM_ * DIM_];
__device__ float g_Wg3r[H_ * H_];
__device__ float g_Wr1r[KH_ * H_];
__device__ float g_Wr2r[KH_ * H_];
__device__ float g_Wg1r[KH_ * H_];
__device__ float g_Wg2r[KH_ * H_];

// ---------------- helpers ----------------------------------------------------
__device__ __forceinline__ uint32_t f2tf32(float x) {
    uint32_t y;
    asm("cvt.rna.tf32.f32 %0, %1;" : "=r"(y) : "f"(x));
    return y;
}
__device__ __forceinline__ float rnd_tf32(float x) {
    return __uint_as_float(f2tf32(x));
}
__device__ __forceinline__ void mma_tf32(float c[4], const uint32_t a[4],
                                         const uint32_t b[2]) {
    asm volatile(
        "mma.sync.aligned.m16n8k8.row.col.f32.tf32.tf32.f32 "
        "{%0,%1,%2,%3}, {%4,%5,%6,%7}, {%8,%9}, {%0,%1,%2,%3};\n"
        : "+f"(c[0]), "+f"(c[1]), "+f"(c[2]), "+f"(c[3])
        : "r"(a[0]), "r"(a[1]), "r"(a[2]), "r"(a[3]), "r"(b[0]), "r"(b[1]));
}
__device__ __forceinline__ void cp16(uint32_t dst, const void* src, bool valid) {
    asm volatile("cp.async.cg.shared.global [%0], [%1], 16, %2;"
                 :: "r"(dst), "l"(src), "r"(valid ? 16 : 0));
}
__device__ __forceinline__ void cp16g(uint32_t dst, const void* src) {
    asm volatile("cp.async.cg.shared.global [%0], [%1], 16;"
                 :: "r"(dst), "l"(src));
}
__device__ __forceinline__ void cp_commit() {
    asm volatile("cp.async.commit_group;");
}
__device__ __forceinline__ void cp_wait0() {
    asm volatile("cp.async.wait_group 0;");
}

// ---------------- tiny kernels ---------------------------------------------
__global__ void zero_pad_kernel() {
    int t = threadIdx.x;                 // 128 threads
    g_convx[N_ * H_ + t] = 0.f;
    g_glo  [N_ * H_ + t] = 0.f;
    g_r1   [N_ * H_ + t] = 0.f;
}

__global__ void round_copy_kernel(const float* __restrict__ src,
                                  float* __restrict__ dst, int n4) {
    int i = blockIdx.x * blockDim.x + threadIdx.x;
    if (i >= n4) return;
    float4 v = reinterpret_cast<const float4*>(src)[i];
    v.x = rnd_tf32(v.x); v.y = rnd_tf32(v.y);
    v.z = rnd_tf32(v.z); v.w = rnd_tf32(v.w);
    reinterpret_cast<float4*>(dst)[i] = v;
}

// round 4 equally-sized weight tensors in one launch (blockIdx.y selects)
__global__ void round4_kernel(const float* __restrict__ s0, float* __restrict__ d0,
                              const float* __restrict__ s1, float* __restrict__ d1,
                              const float* __restrict__ s2, float* __restrict__ d2,
                              const float* __restrict__ s3, float* __restrict__ d3,
                              int n4) {
    int i = blockIdx.x * blockDim.x + threadIdx.x;
    if (i >= n4) return;
    const float* s; float* d;
    switch (blockIdx.y) {
        case 0: s = s0; d = d0; break;
        case 1: s = s1; d = d1; break;
        case 2: s = s2; d = d2; break;
        default: s = s3; d = d3; break;
    }
    float4 v = reinterpret_cast<const float4*>(s)[i];
    v.x = rnd_tf32(v.x); v.y = rnd_tf32(v.y);
    v.z = rnd_tf32(v.z); v.w = rnd_tf32(v.w);
    reinterpret_cast<float4*>(d)[i] = v;
}

// ---------------- sconv: tf32 HMMA, 128x64 output tile per CTA --------------
// C[m, n0:n0+64] = epi( bias + sum_{k,c} A[nbr[m,k], c] * W[k*128+c, n0:] )
// gridDim = (313, 2, nz): y = N-half, z selects (B, bias, C) set (f1/f2 fusion)
enum { EPI_RELU = 0, EPI_R2 = 1 };

constexpr int SBK   = 32;
constexpr int SPA   = SBK + 4;          // 36
constexpr int SPB   = 64 + 8;           // 72
constexpr int SNT   = KH_ / SBK;        // 108
constexpr int SCONV_SMEM = (2 * 128 * SPA + 2 * SBK * SPB + 128 * K_) * 4; // 69120

template <int EPI, int RND>
__global__ void __launch_bounds__(256, 2)
sconv_kernel(const float* __restrict__ A,    // (N_+1) x 128, rounded, zero row N_
             const int* __restrict__ nbr,
             const float* __restrict__ B0,   // [3456][128], rounded
             const float* __restrict__ B1,
             const float* __restrict__ bias0,
             const float* __restrict__ bias1,
             const float* __restrict__ aux,
             float* __restrict__ C0,
             float* __restrict__ C1)
{
    extern __shared__ char smem_raw[];
    float* As   = reinterpret_cast<float*>(smem_raw);        // [2][128][SPA]
    float* Bs   = As + 2 * 128 * SPA;                        // [2][32][SPB]
    int*   snbr = reinterpret_cast<int*>(Bs + 2 * SBK * SPB);// [128][27]

    const int z = blockIdx.z;
    const float* Bm   = z ? B1 : B0;
    const float* bias = z ? bias1 : bias0;
    float*       C    = z ? C1 : C0;

    const int tid  = threadIdx.x;
    const int m0   = blockIdx.x * 128;
    const int n0   = blockIdx.y * 64;
    const int lane = tid & 31;
    const int wid  = tid >> 5;         // 0..7
    const int wm   = wid & 3;          // warp row (4 x 32 = 128)
    const int wn   = wid >> 2;         // warp col (2 x 32 = 64)
    const int g    = lane >> 2;        // 0..7
    const int tg   = lane & 3;         // 0..3

    for (int i = tid; i < 128 * K_; i += 256) {
        int r = i / K_, k = i % K_;
        int row = m0 + r;
        snbr[i] = (row < N_) ? nbr[row * K_ + k] : N_;   // N_ -> zero row
    }
    __syncthreads();

    auto stage = [&](int t, int buf) {
        int k0 = t * SBK;
        int kidx = k0 >> 7;
        int csub = k0 & 127;
        float* Ab = As + buf * 128 * SPA;
        float* Bb = Bs + buf * SBK * SPB;
        // A: 128 rows x 32 cols = 1024 float4
#pragma unroll
        for (int it = 0; it < 4; it++) {
            int idx = tid + it * 256;
            int r   = idx >> 3;            // 0..127
            int c4  = (idx & 7) << 2;      // 0..28
            uint32_t dst = (uint32_t)__cvta_generic_to_shared(&Ab[r * SPA + c4]);
            int src = snbr[r * K_ + kidx];
            cp16g(dst, A + (size_t)src * H_ + csub + c4);
        }
        // B: 32 rows x 64 cols = 512 float4
#pragma unroll
        for (int it = 0; it < 2; it++) {
            int idx = tid + it * 256;
            int r   = idx >> 4;            // 0..31
            int cc  = (idx & 15) << 2;     // 0..60
            uint32_t dst = (uint32_t)__cvta_generic_to_shared(&Bb[r * SPB + cc]);
            cp16g(dst, Bm + (size_t)(k0 + r) * H_ + n0 + cc);
        }
    };

    float acc[2][4][4];
#pragma unroll
    for (int mt = 0; mt < 2; mt++)
#pragma unroll
        for (int nt = 0; nt < 4; nt++)
#pragma unroll
            for (int j = 0; j < 4; j++) acc[mt][nt][j] = 0.f;

    stage(0, 0);
    cp_commit();

    int buf = 0;
    for (int t = 0; t < SNT; t++) {
        cp_wait0();
        __syncthreads();
        if (t + 1 < SNT) { stage(t + 1, buf ^ 1); cp_commit(); }

        const uint32_t* Ab =
            reinterpret_cast<const uint32_t*>(As + buf * 128 * SPA);
        const uint32_t* Bb =
            reinterpret_cast<const uint32_t*>(Bs + buf * SBK * SPB);
#pragma unroll
        for (int ks = 0; ks < SBK; ks += 8) {
            uint32_t bfr[4][2];
#pragma unroll
            for (int nt = 0; nt < 4; nt++) {
                int n = wn * 32 + nt * 8 + g;
                bfr[nt][0] = Bb[(ks + tg)     * SPB + n];
                bfr[nt][1] = Bb[(ks + tg + 4) * SPB + n];
            }
#pragma unroll
            for (int mt = 0; mt < 2; mt++) {
                int m = wm * 32 + mt * 16 + g;
                uint32_t af[4];
                af[0] = Ab[m       * SPA + ks + tg];
                af[1] = Ab[(m + 8) * SPA + ks + tg];
                af[2] = Ab[m       * SPA + ks + tg + 4];
                af[3] = Ab[(m + 8) * SPA + ks + tg + 4];
#pragma unroll
                for (int nt = 0; nt < 4; nt++)
                    mma_tf32(acc[mt][nt], af, bfr[nt]);
            }
        }
        buf ^= 1;
    }

    // ---- epilogue ----
#pragma unroll
    for (int mt = 0; mt < 2; mt++) {
#pragma unroll
        for (int half = 0; half < 2; half++) {
            int row = m0 + wm * 32 + mt * 16 + g + half * 8;
            if (row >= N_) continue;
#pragma unroll
            for (int nt = 0; nt < 4; nt++) {
                int col = n0 + wn * 32 + nt * 8 + tg * 2;
                float v0 = acc[mt][nt][half * 2 + 0] + bias[col];
                float v1 = acc[mt][nt][half * 2 + 1] + bias[col + 1];
                float o0, o1;
                if (EPI == EPI_RELU) {
                    o0 = fmaxf(v0, 0.f);
                    o1 = fmaxf(v1, 0.f);
                } else {  // EPI_R2
                    float2 a = *reinterpret_cast<const float2*>(
                        aux + (size_t)row * H_ + col);
                    o0 = fmaxf(v0, 0.f) + 2.f * a.x;
                    o1 = fmaxf(v1, 0.f) + 2.f * a.y;
                }
                if (RND) { o0 = rnd_tf32(o0); o1 = rnd_tf32(o1); }
                *reinterpret_cast<float2*>(C + (size_t)row * H_ + col) =
                    make_float2(o0, o1);
            }
        }
    }
}

// ---------------- legacy tf32 HMMA GEMM (dense / concat paths) ---------------
enum { AM_DENSE = 0, AM_CONCAT = 2 };
enum { EP_SPLIT = 0, EP_GLO = 3, EP_FINAL = 4 };

constexpr int TILE = 128;
constexpr int BK   = 32;
constexpr int PA   = BK + 4;
constexpr int PB   = TILE + 8;
constexpr int SMEM_BYTES = 2 * TILE * PA * 4 + 2 * BK * PB * 4;

template <int AMODE, int EPI, int RND>
__global__ void __launch_bounds__(256, 2)
gemm_kernel(const float* __restrict__ A, const float* __restrict__ A2,
            const float* __restrict__ Bm, int ldb, int Kdim, int lda,
            const float* __restrict__ bias,
            const float* __restrict__ aux,
            float* __restrict__ C, float* __restrict__ C2)
{
    extern __shared__ char smem_raw[];
    float* As = reinterpret_cast<float*>(smem_raw);          // [2][128][PA]
    float* Bs = As + 2 * TILE * PA;                          // [2][32][PB]

    const int tid = threadIdx.x;
    const int m0  = blockIdx.x * TILE;
    const int n0  = blockIdx.y * TILE;

    const int lane = tid & 31;
    const int wid  = tid >> 5;
    const int wm   = wid & 3;
    const int wn   = wid >> 2;
    const int g    = lane >> 2;
    const int tg   = lane & 3;

    auto stage = [&](int k0, int buf) {
        float* Ab = As + buf * TILE * PA;
        float* Bb = Bs + buf * BK * PB;
#pragma unroll
        for (int it = 0; it < 4; it++) {
            int idx = tid + it * 256;
            int r   = idx >> 3;
            int c4  = (idx & 7) << 2;
            uint32_t dst = (uint32_t)__cvta_generic_to_shared(&Ab[r * PA + c4]);
            if (AMODE == AM_DENSE) {
                int row = m0 + r;
                cp16(dst, A + (size_t)row * lda + k0 + c4, row < N_);
            } else {  // AM_CONCAT
                int row = m0 + r;
                int gc  = k0 + c4;
                const float* srcp = (gc < H_) ? A : A2;
                int cc = (gc < H_) ? gc : gc - H_;
                cp16(dst, srcp + (size_t)row * H_ + cc, row < N_);
            }
        }
#pragma unroll
        for (int it = 0; it < 4; it++) {
            int idx = tid + it * 256;
            int r   = idx >> 5;
            int c4  = (idx & 31) << 2;
            uint32_t dst = (uint32_t)__cvta_generic_to_shared(&Bb[r * PB + c4]);
            cp16(dst, Bm + (size_t)(k0 + r) * ldb + n0 + c4, true);
        }
    };

    float acc[2][8][4];
#pragma unroll
    for (int mt = 0; mt < 2; mt++)
#pragma unroll
        for (int nt = 0; nt < 8; nt++)
#pragma unroll
            for (int j = 0; j < 4; j++) acc[mt][nt][j] = 0.f;

    const int niter = Kdim / BK;
    stage(0, 0);
    cp_commit();

    int buf = 0;
    for (int i = 0; i < niter; i++) {
        cp_wait0();
        __syncthreads();
        if (i + 1 < niter) { stage((i + 1) * BK, buf ^ 1); cp_commit(); }

        const uint32_t* Ab =
            reinterpret_cast<const uint32_t*>(As + buf * TILE * PA);
        const uint32_t* Bb =
            reinterpret_cast<const uint32_t*>(Bs + buf * BK * PB);
#pragma unroll
        for (int ks = 0; ks < BK; ks += 8) {
            uint32_t bfr[8][2];
#pragma unroll
            for (int nt = 0; nt < 8; nt++) {
                int n = wn * 64 + nt * 8 + g;
                bfr[nt][0] = Bb[(ks + tg)     * PB + n];
                bfr[nt][1] = Bb[(ks + tg + 4) * PB + n];
            }
#pragma unroll
            for (int mt = 0; mt < 2; mt++) {
                int m = wm * 32 + mt * 16 + g;
                uint32_t af[4];
                af[0] = Ab[m       * PA + ks + tg];
                af[1] = Ab[(m + 8) * PA + ks + tg];
                af[2] = Ab[m       * PA + ks + tg + 4];
                af[3] = Ab[(m + 8) * PA + ks + tg + 4];
#pragma unroll
                for (int nt = 0; nt < 8; nt++)
                    mma_tf32(acc[mt][nt], af, bfr[nt]);
            }
        }
        buf ^= 1;
    }

#pragma unroll
    for (int mt = 0; mt < 2; mt++) {
#pragma unroll
        for (int half = 0; half < 2; half++) {
            int row = m0 + wm * 32 + mt * 16 + g + half * 8;
            if (row >= N_) continue;
#pragma unroll
            for (int nt = 0; nt < 8; nt++) {
                int col = n0 + wn * 64 + nt * 8 + tg * 2;
                float v0 = acc[mt][nt][half * 2 + 0] + bias[col];
                float v1 = acc[mt][nt][half * 2 + 1] + bias[col + 1];
                if (EPI == EP_SPLIT) {
                    float o0 = RND ? rnd_tf32(v0) : v0;
                    float o1 = RND ? rnd_tf32(v1) : v1;
                    if (col < H_) {
                        C [(size_t)row * H_ + col]     = o0;
                        C [(size_t)row * H_ + col + 1] = o1;
                    } else {
                        C2[(size_t)row * H_ + col - H_]     = o0;
                        C2[(size_t)row * H_ + col - H_ + 1] = o1;
                    }
                } else if (EPI == EP_GLO) {
                    float2 a = *reinterpret_cast<const float2*>(
                        aux + (size_t)row * H_ + col);
                    float o0 = fmaxf(a.x - fmaxf(v0, 0.f), 0.f);
                    float o1 = fmaxf(a.y - fmaxf(v1, 0.f), 0.f);
                    if (RND) { o0 = rnd_tf32(o0); o1 = rnd_tf32(o1); }
                    *reinterpret_cast<float2*>(C + (size_t)row * H_ + col) =
                        make_float2(o0, o1);
                } else {  // EP_FINAL
                    float2 a = *reinterpret_cast<const float2*>(
                        aux + (size_t)row * DIM_ + col);
                    *reinterpret_cast<float2*>(C + (size_t)row * DIM_ + col) =
                        make_float2(a.x + v0, a.y + v1);
                }
            }
        }
    }
}

// ---------------- deterministic segment mean (m2) ---------------------------
__global__ void seg_partial_kernel(const int* __restrict__ bids) {
    int blk = blockIdx.x;
    int o   = threadIdx.x;
    int r0  = blk * CHUNK;
    int r1  = min(r0 + CHUNK, N_);
    float a0 = 0.f, a1 = 0.f, a2 = 0.f, a3 = 0.f;
    for (int r = r0; r < r1; r++) {
        int   b = bids[r];
        float v = g_f2[(size_t)r * H_ + o];
        a0 += (b == 0) ? v : 0.f;
        a1 += (b == 1) ? v : 0.f;
        a2 += (b == 2) ? v : 0.f;
        a3 += (b == 3) ? v : 0.f;
    }
    g_part[(blk * B_ + 0) * H_ + o] = a0;
    g_part[(blk * B_ + 1) * H_ + o] = a1;
    g_part[(blk * B_ + 2) * H_ + o] = a2;
    g_part[(blk * B_ + 3) * H_ + o] = a3;
    if (o < B_) {
        int c = 0;
        for (int r = r0; r < r1; r++) c += (bids[r] == o);
        g_cnt[blk * B_ + o] = c;
    }
}

__global__ void seg_final_kernel() {
    int t = threadIdx.x;
    float s = 0.f;
    for (int p = 0; p < NPART; p++) s += g_part[p * B_ * H_ + t];
    __shared__ int scnt[B_];
    if (t < B_) {
        int c = 0;
        for (int p = 0; p < NPART; p++) c += g_cnt[p * B_ + t];
        scnt[t] = c;
    }
    __syncthreads();
    int b = t / H_;
    float cnt = (float)max(scnt[b], 1);
    g_m2[t] = s / cnt;
}

// ---------------- enc / t = enc + f1 + f2 (stores tf32-rounded) -------------
__global__ void enc_kernel(const int* __restrict__ bids) {
    int warp = threadIdx.x >> 5;
    int lane = threadIdx.x & 31;
    int row  = blockIdx.x * 4 + warp;

    float4 f1v = reinterpret_cast<const float4*>(g_f1 + (size_t)row * H_)[lane];
    float s = f1v.x + f1v.y + f1v.z + f1v.w;
#pragma unroll
    for (int off = 16; off; off >>= 1) s += __shfl_xor_sync(0xffffffffu, s, off);
    float row1 = s * (1.f / 128.f);

    int b = bids[row];
    float4 f2v = reinterpret_cast<const float4*>(g_f2 + (size_t)row * H_)[lane];
    float4 m2v = reinterpret_cast<const float4*>(g_m2 + b * H_)[lane];

    float4 t;
    t.x = rnd_tf32(sqrtf(row1 * m2v.x + 1e-12f) + f1v.x + f2v.x);
    t.y = rnd_tf32(sqrtf(row1 * m2v.y + 1e-12f) + f1v.y + f2v.y);
    t.z = rnd_tf32(sqrtf(row1 * m2v.z + 1e-12f) + f1v.z + f2v.z);
    t.w = rnd_tf32(sqrtf(row1 * m2v.w + 1e-12f) + f1v.w + f2v.w);
    reinterpret_cast<float4*>(g_t + (size_t)row * H_)[lane] = t;
}

// ---------------- launch ----------------------------------------------------
static inline void round_copy(const float* src, float* dst, int n) {
    int n4 = n / 4;
    round_copy_kernel<<<(n4 + 255) / 256, 256>>>(src, dst, n4);
}

extern "C" void kernel_launch(void* const* d_in, const int* in_sizes, int n_in,
                              void* d_out, int out_size)
{
    const float* x    = (const float*)d_in[0];
    const int*   nbr  = (const int*)  d_in[1];
    const int*   bids = (const int*)  d_in[2];
    const float* W1   = (const float*)d_in[3];
    const float* b1   = (const float*)d_in[4];
    const float* W2   = (const float*)d_in[5];
    const float* b2   = (const float*)d_in[6];
    const float* Wr1  = (const float*)d_in[7];
    const float* br1  = (const float*)d_in[8];
    const float* Wr2  = (const float*)d_in[9];
    const float* br2  = (const float*)d_in[10];
    const float* Wg1  = (const float*)d_in[11];
    const float* bg1  = (const float*)d_in[12];
    const float* Wg2  = (const float*)d_in[13];
    const float* bg2  = (const float*)d_in[14];
    const float* Wg3  = (const float*)d_in[15];
    const float* bg3  = (const float*)d_in[16];
    float* out = (float*)d_out;

    float *convx, *glo, *r1, *convout, *f1, *f2, *tb;
    float *xr, *W1r, *W2r, *Wg3r, *Wr1r, *Wr2r, *Wg1r, *Wg2r;
    cudaGetSymbolAddress((void**)&convx,   g_convx);
    cudaGetSymbolAddress((void**)&glo,     g_glo);
    cudaGetSymbolAddress((void**)&r1,      g_r1);
    cudaGetSymbolAddress((void**)&convout, g_convout);
    cudaGetSymbolAddress((void**)&f1,      g_f1);
    cudaGetSymbolAddress((void**)&f2,      g_f2);
    cudaGetSymbolAddress((void**)&tb,      g_t);
    cudaGetSymbolAddress((void**)&xr,      g_xr);
    cudaGetSymbolAddress((void**)&W1r,     g_W1r);
    cudaGetSymbolAddress((void**)&W2r,     g_W2r);
    cudaGetSymbolAddress((void**)&Wg3r,    g_Wg3r);
    cudaGetSymbolAddress((void**)&Wr1r,    g_Wr1r);
    cudaGetSymbolAddress((void**)&Wr2r,    g_Wr2r);
    cudaGetSymbolAddress((void**)&Wg1r,    g_Wg1r);
    cudaGetSymbolAddress((void**)&Wg2r,    g_Wg2r);

    cudaFuncSetAttribute(gemm_kernel<AM_DENSE,  EP_SPLIT, 1>,
                         cudaFuncAttributeMaxDynamicSharedMemorySize, SMEM_BYTES);
    cudaFuncSetAttribute(gemm_kernel<AM_DENSE,  EP_GLO,   1>,
                         cudaFuncAttributeMaxDynamicSharedMemorySize, SMEM_BYTES);
    cudaFuncSetAttribute(gemm_kernel<AM_CONCAT, EP_FINAL, 0>,
                         cudaFuncAttributeMaxDynamicSharedMemorySize, SMEM_BYTES);
    cudaFuncSetAttribute(sconv_kernel<EPI_RELU, 1>,
                         cudaFuncAttributeMaxDynamicSharedMemorySize, SCONV_SMEM);
    cudaFuncSetAttribute(sconv_kernel<EPI_RELU, 0>,
                         cudaFuncAttributeMaxDynamicSharedMemorySize, SCONV_SMEM);
    cudaFuncSetAttribute(sconv_kernel<EPI_R2,   1>,
                         cudaFuncAttributeMaxDynamicSharedMemorySize, SCONV_SMEM);

    const int mt = (N_ + TILE - 1) / TILE;   // 313
    dim3 blk(256);

    // ---- prep: tf32-round all static GEMM operands ----
    round_copy(x,   xr,   N_ * DIM_);
    round_copy(W1,  W1r,  DIM_ * DIM_);
    round_copy(W2,  W2r,  DIM_ * DIM_);
    round_copy(Wg3, Wg3r, H_ * H_);
    {
        int n4 = (KH_ * H_) / 4;
        dim3 g4((n4 + 255) / 256, 4);
        round4_kernel<<<g4, 256>>>(Wr1, Wr1r, Wr2, Wr2r, Wg1, Wg1r, Wg2, Wg2r, n4);
    }
    zero_pad_kernel<<<1, 128>>>();

    // h = x@W1 + b1 ; conv_x = h[:, :128] ; glo = h[:, 128:]  (stored rounded)
    gemm_kernel<AM_DENSE, EP_SPLIT, 1><<<dim3(mt, 2), blk, SMEM_BYTES>>>(
        xr, nullptr, W1r, DIM_, DIM_, DIM_, b1, nullptr, convx, glo);

    // r1 = relu(sconv(conv_x, Wr1, br1))   (N-split grid)
    sconv_kernel<EPI_RELU, 1><<<dim3(mt, 2, 1), blk, SCONV_SMEM>>>(
        convx, nbr, Wr1r, Wr1r, br1, br1, nullptr, r1, r1);

    // convout = relu(sconv(r1, Wr2, br2)) + 2*conv_x
    sconv_kernel<EPI_R2, 1><<<dim3(mt, 2, 1), blk, SCONV_SMEM>>>(
        r1, nbr, Wr2r, Wr2r, br2, br2, convx, convout, convout);

    // f1 = relu(sconv(glo, Wg1, bg1)) ; f2 = relu(sconv(glo, Wg2, bg2))
    // fused into ONE launch (z selects weight/bias/output)
    sconv_kernel<EPI_RELU, 0><<<dim3(mt, 2, 2), blk, SCONV_SMEM>>>(
        glo, nbr, Wg1r, Wg2r, bg1, bg2, nullptr, f1, f2);

    // m2 = segment_mean(f2) (deterministic two-pass)
    seg_partial_kernel<<<NPART, 128>>>(bids);
    seg_final_kernel<<<1, 512>>>();

    // t = sqrt(mean(f1)*m2[bid] + 1e-12) + f1 + f2   (stored rounded)
    enc_kernel<<<N_ / 4, 128>>>(bids);

    // glo = relu(glo - relu(t@Wg3 + bg3))   (stored rounded)
    gemm_kernel<AM_DENSE, EP_GLO, 1><<<dim3(mt, 1), blk, SMEM_BYTES>>>(
        tb, nullptr, Wg3r, H_, H_, H_, bg3, glo, glo, nullptr);

    // out = x + [convout | glo] @ W2 + b2
    gemm_kernel<AM_CONCAT, EP_FINAL, 0><<<dim3(mt, 2), blk, SMEM_BYTES>>>(
        convout, glo, W2r, DIM_, DIM_, 0, b2, x, out, nullptr);
}

// round 14
// speedup vs baseline: 1.8919x; 1.7142x over previous
#include <cuda_runtime.h>
#include <cuda_fp16.h>
#include <math.h>
#include <stdint.h>

// Problem constants (fixed shapes for GCM_60490319396973)
constexpr int N_   = 40000;
constexpr int DIM_ = 256;
constexpr int H_   = 128;
constexpr int K_   = 27;
constexpr int B_   = 4;
constexpr int KH_  = K_ * H_;      // 3456
constexpr int NPART = 250;
constexpr int CHUNK = (N_ + NPART - 1) / NPART;   // 160

// ---------------- scratch (device globals: no allocation allowed) ----------
__device__ __half g_convx[(N_ + 1) * H_];   // padded: row N_ is the zero row
__device__ __half g_glo  [(N_ + 1) * H_];
__device__ __half g_r1   [(N_ + 1) * H_];
__device__ __half g_convout[N_ * H_];
__device__ __half g_t    [N_ * H_];
__device__ __half g_xh   [N_ * DIM_];
__device__ float  g_f1[N_ * H_];
__device__ float  g_f2[N_ * H_];
__device__ float  g_part[NPART * B_ * H_];
__device__ int    g_cnt [NPART * B_];
__device__ float  g_m2  [B_ * H_];
// K-major (transposed) fp16 weights: [n][k]
__device__ __half g_W1t [DIM_ * DIM_];
__device__ __half g_W2t [DIM_ * DIM_];
__device__ __half g_Wg3t[H_ * H_];
__device__ __half g_Wr1t[H_ * KH_];
__device__ __half g_Wr2t[H_ * KH_];
__device__ __half g_Wg1t[H_ * KH_];
__device__ __half g_Wg2t[H_ * KH_];

// ---------------- helpers ----------------------------------------------------
__device__ __forceinline__ void mma_f16(float c[4], const uint32_t a[4],
                                        const uint32_t b[2]) {
    asm volatile(
        "mma.sync.aligned.m16n8k16.row.col.f32.f16.f16.f32 "
        "{%0,%1,%2,%3}, {%4,%5,%6,%7}, {%8,%9}, {%0,%1,%2,%3};\n"
        : "+f"(c[0]), "+f"(c[1]), "+f"(c[2]), "+f"(c[3])
        : "r"(a[0]), "r"(a[1]), "r"(a[2]), "r"(a[3]), "r"(b[0]), "r"(b[1]));
}
__device__ __forceinline__ void cp16(uint32_t dst, const void* src, bool valid) {
    asm volatile("cp.async.cg.shared.global [%0], [%1], 16, %2;"
                 :: "r"(dst), "l"(src), "r"(valid ? 16 : 0));
}
__device__ __forceinline__ void cp16g(uint32_t dst, const void* src) {
    asm volatile("cp.async.cg.shared.global [%0], [%1], 16;"
                 :: "r"(dst), "l"(src));
}
__device__ __forceinline__ void cp_commit() {
    asm volatile("cp.async.commit_group;");
}
__device__ __forceinline__ void cp_wait0() {
    asm volatile("cp.async.wait_group 0;");
}

// ---------------- tiny kernels ---------------------------------------------
__global__ void zero_pad_kernel() {
    int t = threadIdx.x;                 // 128 threads
    g_convx[N_ * H_ + t] = __float2half(0.f);
    g_glo  [N_ * H_ + t] = __float2half(0.f);
    g_r1   [N_ * H_ + t] = __float2half(0.f);
}

// float -> half copy, 8 elements per thread
__global__ void f2h_kernel(const float* __restrict__ src,
                           __half* __restrict__ dst, int n8) {
    int i = blockIdx.x * blockDim.x + threadIdx.x;
    if (i >= n8) return;
    float4 v0 = reinterpret_cast<const float4*>(src)[i * 2];
    float4 v1 = reinterpret_cast<const float4*>(src)[i * 2 + 1];
    __half2* d = reinterpret_cast<__half2*>(dst) + i * 4;
    d[0] = __floats2half2_rn(v0.x, v0.y);
    d[1] = __floats2half2_rn(v0.z, v0.w);
    d[2] = __floats2half2_rn(v1.x, v1.y);
    d[3] = __floats2half2_rn(v1.z, v1.w);
}

// [R][C] float -> [C][R] half transpose
__global__ void transpose_h_kernel(const float* __restrict__ src,
                                   __half* __restrict__ dst, int R, int C) {
    __shared__ float t[32][33];
    int cb = blockIdx.x * 32;
    int rb = blockIdx.y * 32;
    int x = threadIdx.x, y = threadIdx.y;
    for (int i = y; i < 32; i += 8)
        t[i][x] = src[(size_t)(rb + i) * C + cb + x];
    __syncthreads();
    for (int i = y; i < 32; i += 8)
        dst[(size_t)(cb + i) * R + rb + x] = __float2half_rn(t[x][i]);
}

// ---------------- sconv: fp16 HMMA, 128x64 output tile per CTA --------------
// C[m, n0:n0+64] = epi( bias + sum_{k,c} A[nbr[m,k], c] * Wt[n, k*128+c] )
// gridDim = (313, 2, nz): y = N-half, z selects (B, bias, C) set (f1/f2 fusion)
enum { EPI_RELU = 0, EPI_R2 = 1 };

constexpr int SBK  = 64;                 // k per tile (halves)
constexpr int PAW  = 36;                 // A smem pitch in 32-bit words (72 halves)
constexpr int PBW  = 36;                 // B smem pitch in words
constexpr int SNT  = KH_ / SBK;          // 54
constexpr int SCONV_SMEM = (2 * 128 * PAW + 2 * 64 * PBW) * 4 + 128 * K_ * 4; // 69120

template <int EPI, int STOREH>
__global__ void __launch_bounds__(256, 2)
sconv_kernel(const __half* __restrict__ A,   // (N_+1) x 128 half, zero row N_
             const int* __restrict__ nbr,
             const __half* __restrict__ B0,  // [128][3456] half K-major
             const __half* __restrict__ B1,
             const float* __restrict__ bias0,
             const float* __restrict__ bias1,
             const __half* __restrict__ aux,
             void* __restrict__ C0v,
             void* __restrict__ C1v)
{
    extern __shared__ char smem_raw[];
    uint32_t* As32 = reinterpret_cast<uint32_t*>(smem_raw);        // [2][128][PAW]
    uint32_t* Bs32 = As32 + 2 * 128 * PAW;                         // [2][64][PBW]
    int*      snbr = reinterpret_cast<int*>(Bs32 + 2 * 64 * PBW);  // [128][27]

    const int z = blockIdx.z;
    const __half* Bm   = z ? B1 : B0;
    const float*  bias = z ? bias1 : bias0;
    void*         Cv   = z ? C1v : C0v;

    const int tid  = threadIdx.x;
    const int m0   = blockIdx.x * 128;
    const int n0   = blockIdx.y * 64;
    const int lane = tid & 31;
    const int wid  = tid >> 5;         // 0..7
    const int wm   = wid & 3;          // warp row (4 x 32 = 128)
    const int wn   = wid >> 2;         // warp col (2 x 32 = 64)
    const int g    = lane >> 2;        // 0..7
    const int tg   = lane & 3;         // 0..3

    for (int i = tid; i < 128 * K_; i += 256) {
        int r = i / K_, k = i % K_;
        int row = m0 + r;
        snbr[i] = (row < N_) ? nbr[row * K_ + k] : N_;   // N_ -> zero row
    }
    __syncthreads();

    auto stage = [&](int t, int buf) {
        int k0   = t * SBK;
        int kidx = k0 >> 7;
        int csub = k0 & 127;           // 0 or 64
        uint32_t* Ab = As32 + buf * 128 * PAW;
        uint32_t* Bb = Bs32 + buf * 64 * PBW;
        // A: 128 rows x 64 halves = 8 chunks/row = 1024 chunks
#pragma unroll
        for (int it = 0; it < 4; it++) {
            int idx = tid + it * 256;
            int r   = idx >> 3;            // 0..127
            int cu  = idx & 7;             // 16B chunk = 8 halves
            uint32_t dst = (uint32_t)__cvta_generic_to_shared(&Ab[r * PAW + cu * 4]);
            int src = snbr[r * K_ + kidx];
            cp16g(dst, A + (size_t)src * H_ + csub + cu * 8);
        }
        // B: 64 n-rows x 64 halves = 512 chunks
#pragma unroll
        for (int it = 0; it < 2; it++) {
            int idx = tid + it * 256;
            int r   = idx >> 3;            // 0..63
            int cu  = idx & 7;
            uint32_t dst = (uint32_t)__cvta_generic_to_shared(&Bb[r * PBW + cu * 4]);
            cp16g(dst, Bm + (size_t)(n0 + r) * KH_ + k0 + cu * 8);
        }
    };

    float acc[2][4][4];
#pragma unroll
    for (int mt = 0; mt < 2; mt++)
#pragma unroll
        for (int nt = 0; nt < 4; nt++)
#pragma unroll
            for (int j = 0; j < 4; j++) acc[mt][nt][j] = 0.f;

    stage(0, 0);
    cp_commit();

    int buf = 0;
    for (int t = 0; t < SNT; t++) {
        cp_wait0();
        __syncthreads();
        if (t + 1 < SNT) { stage(t + 1, buf ^ 1); cp_commit(); }

        const uint32_t* Ab = As32 + buf * 128 * PAW;
        const uint32_t* Bb = Bs32 + buf * 64 * PBW;
#pragma unroll
        for (int kw = 0; kw < SBK / 2; kw += 8) {   // kw = k/2 word offset
            uint32_t bfr[4][2];
#pragma unroll
            for (int nt = 0; nt < 4; nt++) {
                int n = wn * 32 + nt * 8 + g;
                bfr[nt][0] = Bb[n * PBW + kw + tg];
                bfr[nt][1] = Bb[n * PBW + kw + 4 + tg];
            }
#pragma unroll
            for (int mt = 0; mt < 2; mt++) {
                int m = wm * 32 + mt * 16 + g;
                uint32_t af[4];
                af[0] = Ab[m       * PAW + kw + tg];
                af[1] = Ab[(m + 8) * PAW + kw + tg];
                af[2] = Ab[m       * PAW + kw + 4 + tg];
                af[3] = Ab[(m + 8) * PAW + kw + 4 + tg];
#pragma unroll
                for (int nt = 0; nt < 4; nt++)
                    mma_f16(acc[mt][nt], af, bfr[nt]);
            }
        }
        buf ^= 1;
    }

    // ---- epilogue ----
#pragma unroll
    for (int mt = 0; mt < 2; mt++) {
#pragma unroll
        for (int half = 0; half < 2; half++) {
            int row = m0 + wm * 32 + mt * 16 + g + half * 8;
            if (row >= N_) continue;
#pragma unroll
            for (int nt = 0; nt < 4; nt++) {
                int col = n0 + wn * 32 + nt * 8 + tg * 2;
                float v0 = acc[mt][nt][half * 2 + 0] + bias[col];
                float v1 = acc[mt][nt][half * 2 + 1] + bias[col + 1];
                float o0, o1;
                if (EPI == EPI_RELU) {
                    o0 = fmaxf(v0, 0.f);
                    o1 = fmaxf(v1, 0.f);
                } else {  // EPI_R2
                    float2 a = __half22float2(*reinterpret_cast<const __half2*>(
                        aux + (size_t)row * H_ + col));
                    o0 = fmaxf(v0, 0.f) + 2.f * a.x;
                    o1 = fmaxf(v1, 0.f) + 2.f * a.y;
                }
                if (STOREH) {
                    *reinterpret_cast<__half2*>(
                        reinterpret_cast<__half*>(Cv) + (size_t)row * H_ + col) =
                        __floats2half2_rn(o0, o1);
                } else {
                    *reinterpret_cast<float2*>(
                        reinterpret_cast<float*>(Cv) + (size_t)row * H_ + col) =
                        make_float2(o0, o1);
                }
            }
        }
    }
}

// ---------------- fp16 HMMA GEMM (dense / concat paths), 128x128 tile -------
enum { AM_DENSE = 0, AM_CONCAT = 2 };
enum { EP_SPLIT = 0, EP_GLO = 3, EP_FINAL = 4 };

constexpr int GEMM_SMEM = (2 * 128 * PAW + 2 * 128 * PBW) * 4;   // 73728

template <int AMODE, int EPI>
__global__ void __launch_bounds__(256, 2)
gemm_kernel(const __half* __restrict__ A, const __half* __restrict__ A2,
            const __half* __restrict__ Bt, int Kdim, int lda,
            const float* __restrict__ bias,
            const void* __restrict__ auxv,
            void* __restrict__ Cv, void* __restrict__ C2v)
{
    extern __shared__ char smem_raw[];
    uint32_t* As32 = reinterpret_cast<uint32_t*>(smem_raw);   // [2][128][PAW]
    uint32_t* Bs32 = As32 + 2 * 128 * PAW;                    // [2][128][PBW]

    const int tid = threadIdx.x;
    const int m0  = blockIdx.x * 128;
    const int n0  = blockIdx.y * 128;

    const int lane = tid & 31;
    const int wid  = tid >> 5;
    const int wm   = wid & 3;          // 4 x 32 = 128 rows
    const int wn   = wid >> 2;         // 2 x 64 = 128 cols
    const int g    = lane >> 2;
    const int tg   = lane & 3;

    auto stage = [&](int k0, int buf) {
        uint32_t* Ab = As32 + buf * 128 * PAW;
        uint32_t* Bb = Bs32 + buf * 128 * PBW;
        // A: 128 rows x 64 halves = 1024 chunks
#pragma unroll
        for (int it = 0; it < 4; it++) {
            int idx = tid + it * 256;
            int r   = idx >> 3;
            int cu  = idx & 7;
            uint32_t dst = (uint32_t)__cvta_generic_to_shared(&Ab[r * PAW + cu * 4]);
            int row = m0 + r;
            if (AMODE == AM_DENSE) {
                cp16(dst, A + (size_t)row * lda + k0 + cu * 8, row < N_);
            } else {  // AM_CONCAT (k0 multiple of 64: chunk never straddles)
                int gc = k0 + cu * 8;
                const __half* srcp = (gc < H_) ? A : A2;
                int cc = (gc < H_) ? gc : gc - H_;
                cp16(dst, srcp + (size_t)row * H_ + cc, row < N_);
            }
        }
        // B: 128 n-rows x 64 halves = 1024 chunks
#pragma unroll
        for (int it = 0; it < 4; it++) {
            int idx = tid + it * 256;
            int r   = idx >> 3;
            int cu  = idx & 7;
            uint32_t dst = (uint32_t)__cvta_generic_to_shared(&Bb[r * PBW + cu * 4]);
            cp16g(dst, Bt + (size_t)(n0 + r) * Kdim + k0 + cu * 8);
        }
    };

    float acc[2][8][4];
#pragma unroll
    for (int mt = 0; mt < 2; mt++)
#pragma unroll
        for (int nt = 0; nt < 8; nt++)
#pragma unroll
            for (int j = 0; j < 4; j++) acc[mt][nt][j] = 0.f;

    const int niter = Kdim / SBK;
    stage(0, 0);
    cp_commit();

    int buf = 0;
    for (int i = 0; i < niter; i++) {
        cp_wait0();
        __syncthreads();
        if (i + 1 < niter) { stage((i + 1) * SBK, buf ^ 1); cp_commit(); }

        const uint32_t* Ab = As32 + buf * 128 * PAW;
        const uint32_t* Bb = Bs32 + buf * 128 * PBW;
#pragma unroll
        for (int kw = 0; kw < SBK / 2; kw += 8) {
            uint32_t bfr[8][2];
#pragma unroll
            for (int nt = 0; nt < 8; nt++) {
                int n = wn * 64 + nt * 8 + g;
                bfr[nt][0] = Bb[n * PBW + kw + tg];
                bfr[nt][1] = Bb[n * PBW + kw + 4 + tg];
            }
#pragma unroll
            for (int mt = 0; mt < 2; mt++) {
                int m = wm * 32 + mt * 16 + g;
                uint32_t af[4];
                af[0] = Ab[m       * PAW + kw + tg];
                af[1] = Ab[(m + 8) * PAW + kw + tg];
                af[2] = Ab[m       * PAW + kw + 4 + tg];
                af[3] = Ab[(m + 8) * PAW + kw + 4 + tg];
#pragma unroll
                for (int nt = 0; nt < 8; nt++)
                    mma_f16(acc[mt][nt], af, bfr[nt]);
            }
        }
        buf ^= 1;
    }

#pragma unroll
    for (int mt = 0; mt < 2; mt++) {
#pragma unroll
        for (int half = 0; half < 2; half++) {
            int row = m0 + wm * 32 + mt * 16 + g + half * 8;
            if (row >= N_) continue;
#pragma unroll
            for (int nt = 0; nt < 8; nt++) {
                int col = n0 + wn * 64 + nt * 8 + tg * 2;
                float v0 = acc[mt][nt][half * 2 + 0] + bias[col];
                float v1 = acc[mt][nt][half * 2 + 1] + bias[col + 1];
                if (EPI == EP_SPLIT) {
                    __half2 o = __floats2half2_rn(v0, v1);
                    if (col < H_)
                        *reinterpret_cast<__half2*>(
                            reinterpret_cast<__half*>(Cv) + (size_t)row * H_ + col) = o;
                    else
                        *reinterpret_cast<__half2*>(
                            reinterpret_cast<__half*>(C2v) + (size_t)row * H_ + col - H_) = o;
                } else if (EPI == EP_GLO) {
                    float2 a = __half22float2(*reinterpret_cast<const __half2*>(
                        reinterpret_cast<const __half*>(auxv) + (size_t)row * H_ + col));
                    float o0 = fmaxf(a.x - fmaxf(v0, 0.f), 0.f);
                    float o1 = fmaxf(a.y - fmaxf(v1, 0.f), 0.f);
                    *reinterpret_cast<__half2*>(
                        reinterpret_cast<__half*>(Cv) + (size_t)row * H_ + col) =
                        __floats2half2_rn(o0, o1);
                } else {  // EP_FINAL
                    float2 a = *reinterpret_cast<const float2*>(
                        reinterpret_cast<const float*>(auxv) + (size_t)row * DIM_ + col);
                    *reinterpret_cast<float2*>(
                        reinterpret_cast<float*>(Cv) + (size_t)row * DIM_ + col) =
                        make_float2(a.x + v0, a.y + v1);
                }
            }
        }
    }
}

// ---------------- deterministic segment mean (m2) ---------------------------
__global__ void seg_partial_kernel(const int* __restrict__ bids) {
    int blk = blockIdx.x;
    int o   = threadIdx.x;
    int r0  = blk * CHUNK;
    int r1  = min(r0 + CHUNK, N_);
    float a0 = 0.f, a1 = 0.f, a2 = 0.f, a3 = 0.f;
    for (int r = r0; r < r1; r++) {
        int   b = bids[r];
        float v = g_f2[(size_t)r * H_ + o];
        a0 += (b == 0) ? v : 0.f;
        a1 += (b == 1) ? v : 0.f;
        a2 += (b == 2) ? v : 0.f;
        a3 += (b == 3) ? v : 0.f;
    }
    g_part[(blk * B_ + 0) * H_ + o] = a0;
    g_part[(blk * B_ + 1) * H_ + o] = a1;
    g_part[(blk * B_ + 2) * H_ + o] = a2;
    g_part[(blk * B_ + 3) * H_ + o] = a3;
    if (o < B_) {
        int c = 0;
        for (int r = r0; r < r1; r++) c += (bids[r] == o);
        g_cnt[blk * B_ + o] = c;
    }
}

__global__ void seg_final_kernel() {
    int t = threadIdx.x;
    float s = 0.f;
    for (int p = 0; p < NPART; p++) s += g_part[p * B_ * H_ + t];
    __shared__ int scnt[B_];
    if (t < B_) {
        int c = 0;
        for (int p = 0; p < NPART; p++) c += g_cnt[p * B_ + t];
        scnt[t] = c;
    }
    __syncthreads();
    int b = t / H_;
    float cnt = (float)max(scnt[b], 1);
    g_m2[t] = s / cnt;
}

// ---------------- enc / t = enc + f1 + f2 (stores fp16) ---------------------
__global__ void enc_kernel(const int* __restrict__ bids) {
    int warp = threadIdx.x >> 5;
    int lane = threadIdx.x & 31;
    int row  = blockIdx.x * 4 + warp;

    float4 f1v = reinterpret_cast<const float4*>(g_f1 + (size_t)row * H_)[lane];
    float s = f1v.x + f1v.y + f1v.z + f1v.w;
#pragma unroll
    for (int off = 16; off; off >>= 1) s += __shfl_xor_sync(0xffffffffu, s, off);
    float row1 = s * (1.f / 128.f);

    int b = bids[row];
    float4 f2v = reinterpret_cast<const float4*>(g_f2 + (size_t)row * H_)[lane];
    float4 m2v = reinterpret_cast<const float4*>(g_m2 + b * H_)[lane];

    float t0 = sqrtf(row1 * m2v.x + 1e-12f) + f1v.x + f2v.x;
    float t1 = sqrtf(row1 * m2v.y + 1e-12f) + f1v.y + f2v.y;
    float t2 = sqrtf(row1 * m2v.z + 1e-12f) + f1v.z + f2v.z;
    float t3 = sqrtf(row1 * m2v.w + 1e-12f) + f1v.w + f2v.w;
    __half2* dst = reinterpret_cast<__half2*>(g_t + (size_t)row * H_);
    dst[lane * 2 + 0] = __floats2half2_rn(t0, t1);
    dst[lane * 2 + 1] = __floats2half2_rn(t2, t3);
}

// ---------------- launch ----------------------------------------------------
extern "C" void kernel_launch(void* const* d_in, const int* in_sizes, int n_in,
                              void* d_out, int out_size)
{
    const float* x    = (const float*)d_in[0];
    const int*   nbr  = (const int*)  d_in[1];
    const int*   bids = (const int*)  d_in[2];
    const float* W1   = (const float*)d_in[3];
    const float* b1   = (const float*)d_in[4];
    const float* W2   = (const float*)d_in[5];
    const float* b2   = (const float*)d_in[6];
    const float* Wr1  = (const float*)d_in[7];
    const float* br1  = (const float*)d_in[8];
    const float* Wr2  = (const float*)d_in[9];
    const float* br2  = (const float*)d_in[10];
    const float* Wg1  = (const float*)d_in[11];
    const float* bg1  = (const float*)d_in[12];
    const float* Wg2  = (const float*)d_in[13];
    const float* bg2  = (const float*)d_in[14];
    const float* Wg3  = (const float*)d_in[15];
    const float* bg3  = (const float*)d_in[16];
    float* out = (float*)d_out;

    __half *convx, *glo, *r1, *convout, *tb, *xh;
    __half *W1t, *W2t, *Wg3t, *Wr1t, *Wr2t, *Wg1t, *Wg2t;
    float *f1, *f2;
    cudaGetSymbolAddress((void**)&convx,   g_convx);
    cudaGetSymbolAddress((void**)&glo,     g_glo);
    cudaGetSymbolAddress((void**)&r1,      g_r1);
    cudaGetSymbolAddress((void**)&convout, g_convout);
    cudaGetSymbolAddress((void**)&tb,      g_t);
    cudaGetSymbolAddress((void**)&xh,      g_xh);
    cudaGetSymbolAddress((void**)&f1,      g_f1);
    cudaGetSymbolAddress((void**)&f2,      g_f2);
    cudaGetSymbolAddress((void**)&W1t,     g_W1t);
    cudaGetSymbolAddress((void**)&W2t,     g_W2t);
    cudaGetSymbolAddress((void**)&Wg3t,    g_Wg3t);
    cudaGetSymbolAddress((void**)&Wr1t,    g_Wr1t);
    cudaGetSymbolAddress((void**)&Wr2t,    g_Wr2t);
    cudaGetSymbolAddress((void**)&Wg1t,    g_Wg1t);
    cudaGetSymbolAddress((void**)&Wg2t,    g_Wg2t);

    cudaFuncSetAttribute(gemm_kernel<AM_DENSE,  EP_SPLIT>,
                         cudaFuncAttributeMaxDynamicSharedMemorySize, GEMM_SMEM);
    cudaFuncSetAttribute(gemm_kernel<AM_DENSE,  EP_GLO>,
                         cudaFuncAttributeMaxDynamicSharedMemorySize, GEMM_SMEM);
    cudaFuncSetAttribute(gemm_kernel<AM_CONCAT, EP_FINAL>,
                         cudaFuncAttributeMaxDynamicSharedMemorySize, GEMM_SMEM);
    cudaFuncSetAttribute(sconv_kernel<EPI_RELU, 1>,
                         cudaFuncAttributeMaxDynamicSharedMemorySize, SCONV_SMEM);
    cudaFuncSetAttribute(sconv_kernel<EPI_RELU, 0>,
                         cudaFuncAttributeMaxDynamicSharedMemorySize, SCONV_SMEM);
    cudaFuncSetAttribute(sconv_kernel<EPI_R2,   1>,
                         cudaFuncAttributeMaxDynamicSharedMemorySize, SCONV_SMEM);

    const int mt = (N_ + 127) / 128;   // 313
    dim3 blk(256);

    // ---- prep: fp16 copies / K-major transposes ----
    {
        int n8 = (N_ * DIM_) / 8;
        f2h_kernel<<<(n8 + 255) / 256, 256>>>(x, xh, n8);
    }
    transpose_h_kernel<<<dim3(DIM_ / 32, DIM_ / 32), dim3(32, 8)>>>(W1, W1t, DIM_, DIM_);
    transpose_h_kernel<<<dim3(DIM_ / 32, DIM_ / 32), dim3(32, 8)>>>(W2, W2t, DIM_, DIM_);
    transpose_h_kernel<<<dim3(H_ / 32, H_ / 32), dim3(32, 8)>>>(Wg3, Wg3t, H_, H_);
    transpose_h_kernel<<<dim3(H_ / 32, KH_ / 32), dim3(32, 8)>>>(Wr1, Wr1t, KH_, H_);
    transpose_h_kernel<<<dim3(H_ / 32, KH_ / 32), dim3(32, 8)>>>(Wr2, Wr2t, KH_, H_);
    transpose_h_kernel<<<dim3(H_ / 32, KH_ / 32), dim3(32, 8)>>>(Wg1, Wg1t, KH_, H_);
    transpose_h_kernel<<<dim3(H_ / 32, KH_ / 32), dim3(32, 8)>>>(Wg2, Wg2t, KH_, H_);
    zero_pad_kernel<<<1, 128>>>();

    // h = x@W1 + b1 ; conv_x = h[:, :128] ; glo = h[:, 128:]  (fp16 outputs)
    gemm_kernel<AM_DENSE, EP_SPLIT><<<dim3(mt, 2), blk, GEMM_SMEM>>>(
        xh, nullptr, W1t, DIM_, DIM_, b1, nullptr, convx, glo);

    // r1 = relu(sconv(conv_x, Wr1, br1))
    sconv_kernel<EPI_RELU, 1><<<dim3(mt, 2, 1), blk, SCONV_SMEM>>>(
        convx, nbr, Wr1t, Wr1t, br1, br1, nullptr, r1, r1);

    // convout = relu(sconv(r1, Wr2, br2)) + 2*conv_x
    sconv_kernel<EPI_R2, 1><<<dim3(mt, 2, 1), blk, SCONV_SMEM>>>(
        r1, nbr, Wr2t, Wr2t, br2, br2, convx, convout, convout);

    // f1 / f2 fused in one launch (fp32 outputs for exact seg/enc path)
    sconv_kernel<EPI_RELU, 0><<<dim3(mt, 2, 2), blk, SCONV_SMEM>>>(
        glo, nbr, Wg1t, Wg2t, bg1, bg2, nullptr, f1, f2);

    // m2 = segment_mean(f2) (deterministic two-pass)
    seg_partial_kernel<<<NPART, 128>>>(bids);
    seg_final_kernel<<<1, 512>>>();

    // t = sqrt(mean(f1)*m2[bid] + 1e-12) + f1 + f2   (fp16 output)
    enc_kernel<<<N_ / 4, 128>>>(bids);

    // glo = relu(glo - relu(t@Wg3 + bg3))   (fp16 in/out)
    gemm_kernel<AM_DENSE, EP_GLO><<<dim3(mt, 1), blk, GEMM_SMEM>>>(
        tb, nullptr, Wg3t, H_, H_, bg3, glo, glo, nullptr);

    // out = x + [convout | glo] @ W2 + b2   (fp32 output)
    gemm_kernel<AM_CONCAT, EP_FINAL><<<dim3(mt, 2), blk, GEMM_SMEM>>>(
        convout, glo, W2t, DIM_, 0, b2, x, out, nullptr);
}

// round 15
// speedup vs baseline: 2.0960x; 1.1079x over previous
#include <cuda_runtime.h>
#include <cuda_fp16.h>
#include <math.h>
#include <stdint.h>

// Problem constants (fixed shapes for GCM_60490319396973)
constexpr int N_   = 40000;
constexpr int DIM_ = 256;
constexpr int H_   = 128;
constexpr int K_   = 27;
constexpr int B_   = 4;
constexpr int KH_  = K_ * H_;      // 3456
constexpr int NPART = 250;
constexpr int CHUNK = (N_ + NPART - 1) / NPART;   // 160

// ---------------- scratch (device globals: no allocation allowed) ----------
__device__ __half g_convx[(N_ + 1) * H_];   // padded: row N_ is the zero row
__device__ __half g_glo  [(N_ + 1) * H_];
__device__ __half g_r1   [(N_ + 1) * H_];
__device__ __half g_convout[N_ * H_];
__device__ __half g_t    [N_ * H_];
__device__ __half g_xh   [N_ * DIM_];
__device__ float  g_f1[N_ * H_];
__device__ float  g_f2[N_ * H_];
__device__ float  g_part[NPART * B_ * H_];
__device__ int    g_cnt [NPART * B_];
__device__ float  g_m2  [B_ * H_];
// K-major (transposed) fp16 weights: [n][k]
__device__ __half g_W1t [DIM_ * DIM_];
__device__ __half g_W2t [DIM_ * DIM_];
__device__ __half g_Wg3t[H_ * H_];
__device__ __half g_Wr1t[H_ * KH_];
__device__ __half g_Wr2t[H_ * KH_];
__device__ __half g_Wg1t[H_ * KH_];
__device__ __half g_Wg2t[H_ * KH_];

// ---------------- helpers ----------------------------------------------------
__device__ __forceinline__ void mma_f16(float c[4], const uint32_t a[4],
                                        const uint32_t b[2]) {
    asm volatile(
        "mma.sync.aligned.m16n8k16.row.col.f32.f16.f16.f32 "
        "{%0,%1,%2,%3}, {%4,%5,%6,%7}, {%8,%9}, {%0,%1,%2,%3};\n"
        : "+f"(c[0]), "+f"(c[1]), "+f"(c[2]), "+f"(c[3])
        : "r"(a[0]), "r"(a[1]), "r"(a[2]), "r"(a[3]), "r"(b[0]), "r"(b[1]));
}
__device__ __forceinline__ void ldsm4(uint32_t& a, uint32_t& b,
                                      uint32_t& c, uint32_t& d, uint32_t addr) {
    asm volatile("ldmatrix.sync.aligned.m8n8.x4.shared.b16 {%0,%1,%2,%3}, [%4];"
                 : "=r"(a), "=r"(b), "=r"(c), "=r"(d) : "r"(addr));
}
__device__ __forceinline__ void cp16(uint32_t dst, const void* src, bool valid) {
    asm volatile("cp.async.cg.shared.global [%0], [%1], 16, %2;"
                 :: "r"(dst), "l"(src), "r"(valid ? 16 : 0));
}
__device__ __forceinline__ void cp16g(uint32_t dst, const void* src) {
    asm volatile("cp.async.cg.shared.global [%0], [%1], 16;"
                 :: "r"(dst), "l"(src));
}
__device__ __forceinline__ void cp_commit() {
    asm volatile("cp.async.commit_group;");
}
__device__ __forceinline__ void cp_wait0() {
    asm volatile("cp.async.wait_group 0;");
}

// ---------------- tiny kernels ---------------------------------------------
__global__ void zero_pad_kernel() {
    int t = threadIdx.x;                 // 128 threads
    g_convx[N_ * H_ + t] = __float2half(0.f);
    g_glo  [N_ * H_ + t] = __float2half(0.f);
    g_r1   [N_ * H_ + t] = __float2half(0.f);
}

// float -> half copy, 8 elements per thread
__global__ void f2h_kernel(const float* __restrict__ src,
                           __half* __restrict__ dst, int n8) {
    int i = blockIdx.x * blockDim.x + threadIdx.x;
    if (i >= n8) return;
    float4 v0 = reinterpret_cast<const float4*>(src)[i * 2];
    float4 v1 = reinterpret_cast<const float4*>(src)[i * 2 + 1];
    __half2* d = reinterpret_cast<__half2*>(dst) + i * 4;
    d[0] = __floats2half2_rn(v0.x, v0.y);
    d[1] = __floats2half2_rn(v0.z, v0.w);
    d[2] = __floats2half2_rn(v1.x, v1.y);
    d[3] = __floats2half2_rn(v1.z, v1.w);
}

// [R][C] float -> [C][R] half transpose
__global__ void transpose_h_kernel(const float* __restrict__ src,
                                   __half* __restrict__ dst, int R, int C) {
    __shared__ float t[32][33];
    int cb = blockIdx.x * 32;
    int rb = blockIdx.y * 32;
    int x = threadIdx.x, y = threadIdx.y;
    for (int i = y; i < 32; i += 8)
        t[i][x] = src[(size_t)(rb + i) * C + cb + x];
    __syncthreads();
    for (int i = y; i < 32; i += 8)
        dst[(size_t)(cb + i) * R + rb + x] = __float2half_rn(t[x][i]);
}

// ---------------- sconv: fp16 HMMA + ldmatrix, 128x64 tile per CTA ----------
// C[m, n0:n0+64] = epi( bias + sum_{k,c} A[nbr[m,k], c] * Wt[n, k*128+c] )
// gridDim = (313, 2, nz): y = N-half, z selects (B, bias, C) set (f1/f2 fusion)
enum { EPI_RELU = 0, EPI_R2 = 1 };

constexpr int SBK  = 64;                 // k per tile (halves)
constexpr int PAW  = 36;                 // A smem pitch in 32-bit words (72 halves)
constexpr int PBW  = 36;                 // B smem pitch in words
constexpr int SNT  = KH_ / SBK;          // 54
constexpr int ROWB = PAW * 4;            // 144 bytes per smem row
constexpr int SCONV_SMEM = (2 * 128 * PAW + 2 * 64 * PBW) * 4 + 128 * K_ * 4; // 69120

template <int EPI, int STOREH>
__global__ void __launch_bounds__(256, 2)
sconv_kernel(const __half* __restrict__ A,   // (N_+1) x 128 half, zero row N_
             const int* __restrict__ nbr,
             const __half* __restrict__ B0,  // [128][3456] half K-major
             const __half* __restrict__ B1,
             const float* __restrict__ bias0,
             const float* __restrict__ bias1,
             const __half* __restrict__ aux,
             void* __restrict__ C0v,
             void* __restrict__ C1v)
{
    extern __shared__ char smem_raw[];
    uint32_t* As32 = reinterpret_cast<uint32_t*>(smem_raw);        // [2][128][PAW]
    uint32_t* Bs32 = As32 + 2 * 128 * PAW;                         // [2][64][PBW]
    int*      snbr = reinterpret_cast<int*>(Bs32 + 2 * 64 * PBW);  // [128][27]

    const int z = blockIdx.z;
    const __half* Bm   = z ? B1 : B0;
    const float*  bias = z ? bias1 : bias0;
    void*         Cv   = z ? C1v : C0v;

    const int tid  = threadIdx.x;
    const int m0   = blockIdx.x * 128;
    const int n0   = blockIdx.y * 64;
    const int lane = tid & 31;
    const int wid  = tid >> 5;         // 0..7
    const int wm   = wid & 3;          // warp row (4 x 32 = 128)
    const int wn   = wid >> 2;         // warp col (2 x 32 = 64)
    const int g    = lane >> 2;        // 0..7
    const int tg   = lane & 3;         // 0..3

    // ldmatrix lane geometry: j = quad index, rr = row within 8x8 tile
    const int lj = lane >> 3;          // 0..3
    const int rr = lane & 7;

    for (int i = tid; i < 128 * K_; i += 256) {
        int r = i / K_, k = i % K_;
        int row = m0 + r;
        snbr[i] = (row < N_) ? nbr[row * K_ + k] : N_;   // N_ -> zero row
    }
    __syncthreads();

    auto stage = [&](int t, int buf) {
        int k0   = t * SBK;
        int kidx = k0 >> 7;
        int csub = k0 & 127;           // 0 or 64
        uint32_t* Ab = As32 + buf * 128 * PAW;
        uint32_t* Bb = Bs32 + buf * 64 * PBW;
#pragma unroll
        for (int it = 0; it < 4; it++) {
            int idx = tid + it * 256;
            int r   = idx >> 3;            // 0..127
            int cu  = idx & 7;             // 16B chunk = 8 halves
            uint32_t dst = (uint32_t)__cvta_generic_to_shared(&Ab[r * PAW + cu * 4]);
            int src = snbr[r * K_ + kidx];
            cp16g(dst, A + (size_t)src * H_ + csub + cu * 8);
        }
#pragma unroll
        for (int it = 0; it < 2; it++) {
            int idx = tid + it * 256;
            int r   = idx >> 3;            // 0..63
            int cu  = idx & 7;
            uint32_t dst = (uint32_t)__cvta_generic_to_shared(&Bb[r * PBW + cu * 4]);
            cp16g(dst, Bm + (size_t)(n0 + r) * KH_ + k0 + cu * 8);
        }
    };

    float acc[2][4][4];
#pragma unroll
    for (int mt = 0; mt < 2; mt++)
#pragma unroll
        for (int nt = 0; nt < 4; nt++)
#pragma unroll
            for (int j = 0; j < 4; j++) acc[mt][nt][j] = 0.f;

    stage(0, 0);
    cp_commit();

    int buf = 0;
    for (int t = 0; t < SNT; t++) {
        cp_wait0();
        __syncthreads();
        if (t + 1 < SNT) { stage(t + 1, buf ^ 1); cp_commit(); }

        // per-lane ldmatrix base addresses (bytes)
        uint32_t aB = (uint32_t)__cvta_generic_to_shared(As32 + buf * 128 * PAW)
                    + (uint32_t)(wm * 32 + (lj & 1) * 8 + rr) * ROWB
                    + (uint32_t)((lj >> 1) * 8) * 2;
        uint32_t bB = (uint32_t)__cvta_generic_to_shared(Bs32 + buf * 64 * PBW)
                    + (uint32_t)(wn * 32 + (lj >> 1) * 8 + rr) * ROWB
                    + (uint32_t)((lj & 1) * 8) * 2;
#pragma unroll
        for (int kw = 0; kw < SBK / 2; kw += 8) {   // kw = k/2 word offset
            uint32_t kb = kw * 4;                    // byte offset
            uint32_t a0[4], a1[4];
            ldsm4(a0[0], a0[1], a0[2], a0[3], aB + kb);
            ldsm4(a1[0], a1[1], a1[2], a1[3], aB + 16 * ROWB + kb);
            uint32_t bv[8];
            ldsm4(bv[0], bv[1], bv[2], bv[3], bB + kb);              // nt 0,1
            ldsm4(bv[4], bv[5], bv[6], bv[7], bB + 16 * ROWB + kb);  // nt 2,3
#pragma unroll
            for (int nt = 0; nt < 4; nt++) {
                mma_f16(acc[0][nt], a0, bv + nt * 2);
                mma_f16(acc[1][nt], a1, bv + nt * 2);
            }
        }
        buf ^= 1;
    }

    // ---- epilogue ----
#pragma unroll
    for (int mt = 0; mt < 2; mt++) {
#pragma unroll
        for (int half = 0; half < 2; half++) {
            int row = m0 + wm * 32 + mt * 16 + g + half * 8;
            if (row >= N_) continue;
#pragma unroll
            for (int nt = 0; nt < 4; nt++) {
                int col = n0 + wn * 32 + nt * 8 + tg * 2;
                float v0 = acc[mt][nt][half * 2 + 0] + bias[col];
                float v1 = acc[mt][nt][half * 2 + 1] + bias[col + 1];
                float o0, o1;
                if (EPI == EPI_RELU) {
                    o0 = fmaxf(v0, 0.f);
                    o1 = fmaxf(v1, 0.f);
                } else {  // EPI_R2
                    float2 a = __half22float2(*reinterpret_cast<const __half2*>(
                        aux + (size_t)row * H_ + col));
                    o0 = fmaxf(v0, 0.f) + 2.f * a.x;
                    o1 = fmaxf(v1, 0.f) + 2.f * a.y;
                }
                if (STOREH) {
                    *reinterpret_cast<__half2*>(
                        reinterpret_cast<__half*>(Cv) + (size_t)row * H_ + col) =
                        __floats2half2_rn(o0, o1);
                } else {
                    *reinterpret_cast<float2*>(
                        reinterpret_cast<float*>(Cv) + (size_t)row * H_ + col) =
                        make_float2(o0, o1);
                }
            }
        }
    }
}

// ---------------- fp16 HMMA GEMM (dense / concat paths), 128x128 tile -------
enum { AM_DENSE = 0, AM_CONCAT = 2 };
enum { EP_SPLIT = 0, EP_GLO = 3, EP_FINAL = 4 };

constexpr int GEMM_SMEM = (2 * 128 * PAW + 2 * 128 * PBW) * 4;   // 73728

template <int AMODE, int EPI>
__global__ void __launch_bounds__(256, 2)
gemm_kernel(const __half* __restrict__ A, const __half* __restrict__ A2,
            const __half* __restrict__ Bt, int Kdim, int lda,
            const float* __restrict__ bias,
            const void* __restrict__ auxv,
            void* __restrict__ Cv, void* __restrict__ C2v)
{
    extern __shared__ char smem_raw[];
    uint32_t* As32 = reinterpret_cast<uint32_t*>(smem_raw);   // [2][128][PAW]
    uint32_t* Bs32 = As32 + 2 * 128 * PAW;                    // [2][128][PBW]

    const int tid = threadIdx.x;
    const int m0  = blockIdx.x * 128;
    const int n0  = blockIdx.y * 128;

    const int lane = tid & 31;
    const int wid  = tid >> 5;
    const int wm   = wid & 3;          // 4 x 32 = 128 rows
    const int wn   = wid >> 2;         // 2 x 64 = 128 cols
    const int g    = lane >> 2;
    const int tg   = lane & 3;
    const int lj   = lane >> 3;
    const int rr   = lane & 7;

    auto stage = [&](int k0, int buf) {
        uint32_t* Ab = As32 + buf * 128 * PAW;
        uint32_t* Bb = Bs32 + buf * 128 * PBW;
#pragma unroll
        for (int it = 0; it < 4; it++) {
            int idx = tid + it * 256;
            int r   = idx >> 3;
            int cu  = idx & 7;
            uint32_t dst = (uint32_t)__cvta_generic_to_shared(&Ab[r * PAW + cu * 4]);
            int row = m0 + r;
            if (AMODE == AM_DENSE) {
                cp16(dst, A + (size_t)row * lda + k0 + cu * 8, row < N_);
            } else {  // AM_CONCAT (k0 multiple of 64: chunk never straddles)
                int gc = k0 + cu * 8;
                const __half* srcp = (gc < H_) ? A : A2;
                int cc = (gc < H_) ? gc : gc - H_;
                cp16(dst, srcp + (size_t)row * H_ + cc, row < N_);
            }
        }
#pragma unroll
        for (int it = 0; it < 4; it++) {
            int idx = tid + it * 256;
            int r   = idx >> 3;
            int cu  = idx & 7;
            uint32_t dst = (uint32_t)__cvta_generic_to_shared(&Bb[r * PBW + cu * 4]);
            cp16g(dst, Bt + (size_t)(n0 + r) * Kdim + k0 + cu * 8);
        }
    };

    float acc[2][8][4];
#pragma unroll
    for (int mt = 0; mt < 2; mt++)
#pragma unroll
        for (int nt = 0; nt < 8; nt++)
#pragma unroll
            for (int j = 0; j < 4; j++) acc[mt][nt][j] = 0.f;

    const int niter = Kdim / SBK;
    stage(0, 0);
    cp_commit();

    int buf = 0;
    for (int i = 0; i < niter; i++) {
        cp_wait0();
        __syncthreads();
        if (i + 1 < niter) { stage((i + 1) * SBK, buf ^ 1); cp_commit(); }

        uint32_t aB = (uint32_t)__cvta_generic_to_shared(As32 + buf * 128 * PAW)
                    + (uint32_t)(wm * 32 + (lj & 1) * 8 + rr) * ROWB
                    + (uint32_t)((lj >> 1) * 8) * 2;
        uint32_t bB = (uint32_t)__cvta_generic_to_shared(Bs32 + buf * 128 * PBW)
                    + (uint32_t)(wn * 64 + (lj >> 1) * 8 + rr) * ROWB
                    + (uint32_t)((lj & 1) * 8) * 2;
#pragma unroll
        for (int kw = 0; kw < SBK / 2; kw += 8) {
            uint32_t kb = kw * 4;
            uint32_t a0[4], a1[4];
            ldsm4(a0[0], a0[1], a0[2], a0[3], aB + kb);
            ldsm4(a1[0], a1[1], a1[2], a1[3], aB + 16 * ROWB + kb);
            uint32_t bv[16];
#pragma unroll
            for (int p = 0; p < 4; p++)
                ldsm4(bv[p * 4 + 0], bv[p * 4 + 1], bv[p * 4 + 2], bv[p * 4 + 3],
                      bB + (uint32_t)p * 16 * ROWB + kb);
#pragma unroll
            for (int nt = 0; nt < 8; nt++) {
                mma_f16(acc[0][nt], a0, bv + nt * 2);
                mma_f16(acc[1][nt], a1, bv + nt * 2);
            }
        }
        buf ^= 1;
    }

#pragma unroll
    for (int mt = 0; mt < 2; mt++) {
#pragma unroll
        for (int half = 0; half < 2; half++) {
            int row = m0 + wm * 32 + mt * 16 + g + half * 8;
            if (row >= N_) continue;
#pragma unroll
            for (int nt = 0; nt < 8; nt++) {
                int col = n0 + wn * 64 + nt * 8 + tg * 2;
                float v0 = acc[mt][nt][half * 2 + 0] + bias[col];
                float v1 = acc[mt][nt][half * 2 + 1] + bias[col + 1];
                if (EPI == EP_SPLIT) {
                    __half2 o = __floats2half2_rn(v0, v1);
                    if (col < H_)
                        *reinterpret_cast<__half2*>(
                            reinterpret_cast<__half*>(Cv) + (size_t)row * H_ + col) = o;
                    else
                        *reinterpret_cast<__half2*>(
                            reinterpret_cast<__half*>(C2v) + (size_t)row * H_ + col - H_) = o;
                } else if (EPI == EP_GLO) {
                    float2 a = __half22float2(*reinterpret_cast<const __half2*>(
                        reinterpret_cast<const __half*>(auxv) + (size_t)row * H_ + col));
                    float o0 = fmaxf(a.x - fmaxf(v0, 0.f), 0.f);
                    float o1 = fmaxf(a.y - fmaxf(v1, 0.f), 0.f);
                    *reinterpret_cast<__half2*>(
                        reinterpret_cast<__half*>(Cv) + (size_t)row * H_ + col) =
                        __floats2half2_rn(o0, o1);
                } else {  // EP_FINAL
                    float2 a = *reinterpret_cast<const float2*>(
                        reinterpret_cast<const float*>(auxv) + (size_t)row * DIM_ + col);
                    *reinterpret_cast<float2*>(
                        reinterpret_cast<float*>(Cv) + (size_t)row * DIM_ + col) =
                        make_float2(a.x + v0, a.y + v1);
                }
            }
        }
    }
}

// ---------------- deterministic segment mean (m2) ---------------------------
__global__ void seg_partial_kernel(const int* __restrict__ bids) {
    int blk = blockIdx.x;
    int o   = threadIdx.x;
    int r0  = blk * CHUNK;
    int r1  = min(r0 + CHUNK, N_);
    float a0 = 0.f, a1 = 0.f, a2 = 0.f, a3 = 0.f;
    for (int r = r0; r < r1; r++) {
        int   b = bids[r];
        float v = g_f2[(size_t)r * H_ + o];
        a0 += (b == 0) ? v : 0.f;
        a1 += (b == 1) ? v : 0.f;
        a2 += (b == 2) ? v : 0.f;
        a3 += (b == 3) ? v : 0.f;
    }
    g_part[(blk * B_ + 0) * H_ + o] = a0;
    g_part[(blk * B_ + 1) * H_ + o] = a1;
    g_part[(blk * B_ + 2) * H_ + o] = a2;
    g_part[(blk * B_ + 3) * H_ + o] = a3;
    if (o < B_) {
        int c = 0;
        for (int r = r0; r < r1; r++) c += (bids[r] == o);
        g_cnt[blk * B_ + o] = c;
    }
}

__global__ void seg_final_kernel() {
    int t = threadIdx.x;
    float s = 0.f;
    for (int p = 0; p < NPART; p++) s += g_part[p * B_ * H_ + t];
    __shared__ int scnt[B_];
    if (t < B_) {
        int c = 0;
        for (int p = 0; p < NPART; p++) c += g_cnt[p * B_ + t];
        scnt[t] = c;
    }
    __syncthreads();
    int b = t / H_;
    float cnt = (float)max(scnt[b], 1);
    g_m2[t] = s / cnt;
}

// ---------------- enc / t = enc + f1 + f2 (stores fp16) ---------------------
__global__ void enc_kernel(const int* __restrict__ bids) {
    int warp = threadIdx.x >> 5;
    int lane = threadIdx.x & 31;
    int row  = blockIdx.x * 4 + warp;

    float4 f1v = reinterpret_cast<const float4*>(g_f1 + (size_t)row * H_)[lane];
    float s = f1v.x + f1v.y + f1v.z + f1v.w;
#pragma unroll
    for (int off = 16; off; off >>= 1) s += __shfl_xor_sync(0xffffffffu, s, off);
    float row1 = s * (1.f / 128.f);

    int b = bids[row];
    float4 f2v = reinterpret_cast<const float4*>(g_f2 + (size_t)row * H_)[lane];
    float4 m2v = reinterpret_cast<const float4*>(g_m2 + b * H_)[lane];

    float t0 = sqrtf(row1 * m2v.x + 1e-12f) + f1v.x + f2v.x;
    float t1 = sqrtf(row1 * m2v.y + 1e-12f) + f1v.y + f2v.y;
    float t2 = sqrtf(row1 * m2v.z + 1e-12f) + f1v.z + f2v.z;
    float t3 = sqrtf(row1 * m2v.w + 1e-12f) + f1v.w + f2v.w;
    __half2* dst = reinterpret_cast<__half2*>(g_t + (size_t)row * H_);
    dst[lane * 2 + 0] = __floats2half2_rn(t0, t1);
    dst[lane * 2 + 1] = __floats2half2_rn(t2, t3);
}

// ---------------- launch ----------------------------------------------------
extern "C" void kernel_launch(void* const* d_in, const int* in_sizes, int n_in,
                              void* d_out, int out_size)
{
    const float* x    = (const float*)d_in[0];
    const int*   nbr  = (const int*)  d_in[1];
    const int*   bids = (const int*)  d_in[2];
    const float* W1   = (const float*)d_in[3];
    const float* b1   = (const float*)d_in[4];
    const float* W2   = (const float*)d_in[5];
    const float* b2   = (const float*)d_in[6];
    const float* Wr1  = (const float*)d_in[7];
    const float* br1  = (const float*)d_in[8];
    const float* Wr2  = (const float*)d_in[9];
    const float* br2  = (const float*)d_in[10];
    const float* Wg1  = (const float*)d_in[11];
    const float* bg1  = (const float*)d_in[12];
    const float* Wg2  = (const float*)d_in[13];
    const float* bg2  = (const float*)d_in[14];
    const float* Wg3  = (const float*)d_in[15];
    const float* bg3  = (const float*)d_in[16];
    float* out = (float*)d_out;

    __half *convx, *glo, *r1, *convout, *tb, *xh;
    __half *W1t, *W2t, *Wg3t, *Wr1t, *Wr2t, *Wg1t, *Wg2t;
    float *f1, *f2;
    cudaGetSymbolAddress((void**)&convx,   g_convx);
    cudaGetSymbolAddress((void**)&glo,     g_glo);
    cudaGetSymbolAddress((void**)&r1,      g_r1);
    cudaGetSymbolAddress((void**)&convout, g_convout);
    cudaGetSymbolAddress((void**)&tb,      g_t);
    cudaGetSymbolAddress((void**)&xh,      g_xh);
    cudaGetSymbolAddress((void**)&f1,      g_f1);
    cudaGetSymbolAddress((void**)&f2,      g_f2);
    cudaGetSymbolAddress((void**)&W1t,     g_W1t);
    cudaGetSymbolAddress((void**)&W2t,     g_W2t);
    cudaGetSymbolAddress((void**)&Wg3t,    g_Wg3t);
    cudaGetSymbolAddress((void**)&Wr1t,    g_Wr1t);
    cudaGetSymbolAddress((void**)&Wr2t,    g_Wr2t);
    cudaGetSymbolAddress((void**)&Wg1t,    g_Wg1t);
    cudaGetSymbolAddress((void**)&Wg2t,    g_Wg2t);

    cudaFuncSetAttribute(gemm_kernel<AM_DENSE,  EP_SPLIT>,
                         cudaFuncAttributeMaxDynamicSharedMemorySize, GEMM_SMEM);
    cudaFuncSetAttribute(gemm_kernel<AM_DENSE,  EP_GLO>,
                         cudaFuncAttributeMaxDynamicSharedMemorySize, GEMM_SMEM);
    cudaFuncSetAttribute(gemm_kernel<AM_CONCAT, EP_FINAL>,
                         cudaFuncAttributeMaxDynamicSharedMemorySize, GEMM_SMEM);
    cudaFuncSetAttribute(sconv_kernel<EPI_RELU, 1>,
                         cudaFuncAttributeMaxDynamicSharedMemorySize, SCONV_SMEM);
    cudaFuncSetAttribute(sconv_kernel<EPI_RELU, 0>,
                         cudaFuncAttributeMaxDynamicSharedMemorySize, SCONV_SMEM);
    cudaFuncSetAttribute(sconv_kernel<EPI_R2,   1>,
                         cudaFuncAttributeMaxDynamicSharedMemorySize, SCONV_SMEM);

    const int mt = (N_ + 127) / 128;   // 313
    dim3 blk(256);

    // ---- prep: fp16 copies / K-major transposes ----
    {
        int n8 = (N_ * DIM_) / 8;
        f2h_kernel<<<(n8 + 255) / 256, 256>>>(x, xh, n8);
    }
    transpose_h_kernel<<<dim3(DIM_ / 32, DIM_ / 32), dim3(32, 8)>>>(W1, W1t, DIM_, DIM_);
    transpose_h_kernel<<<dim3(DIM_ / 32, DIM_ / 32), dim3(32, 8)>>>(W2, W2t, DIM_, DIM_);
    transpose_h_kernel<<<dim3(H_ / 32, H_ / 32), dim3(32, 8)>>>(Wg3, Wg3t, H_, H_);
    transpose_h_kernel<<<dim3(H_ / 32, KH_ / 32), dim3(32, 8)>>>(Wr1, Wr1t, KH_, H_);
    transpose_h_kernel<<<dim3(H_ / 32, KH_ / 32), dim3(32, 8)>>>(Wr2, Wr2t, KH_, H_);
    transpose_h_kernel<<<dim3(H_ / 32, KH_ / 32), dim3(32, 8)>>>(Wg1, Wg1t, KH_, H_);
    transpose_h_kernel<<<dim3(H_ / 32, KH_ / 32), dim3(32, 8)>>>(Wg2, Wg2t, KH_, H_);
    zero_pad_kernel<<<1, 128>>>();

    // h = x@W1 + b1 ; conv_x = h[:, :128] ; glo = h[:, 128:]  (fp16 outputs)
    gemm_kernel<AM_DENSE, EP_SPLIT><<<dim3(mt, 2), blk, GEMM_SMEM>>>(
        xh, nullptr, W1t, DIM_, DIM_, b1, nullptr, convx, glo);

    // r1 = relu(sconv(conv_x, Wr1, br1))
    sconv_kernel<EPI_RELU, 1><<<dim3(mt, 2, 1), blk, SCONV_SMEM>>>(
        convx, nbr, Wr1t, Wr1t, br1, br1, nullptr, r1, r1);

    // convout = relu(sconv(r1, Wr2, br2)) + 2*conv_x
    sconv_kernel<EPI_R2, 1><<<dim3(mt, 2, 1), blk, SCONV_SMEM>>>(
        r1, nbr, Wr2t, Wr2t, br2, br2, convx, convout, convout);

    // f1 / f2 fused in one launch (fp32 outputs for exact seg/enc path)
    sconv_kernel<EPI_RELU, 0><<<dim3(mt, 2, 2), blk, SCONV_SMEM>>>(
        glo, nbr, Wg1t, Wg2t, bg1, bg2, nullptr, f1, f2);

    // m2 = segment_mean(f2) (deterministic two-pass)
    seg_partial_kernel<<<NPART, 128>>>(bids);
    seg_final_kernel<<<1, 512>>>();

    // t = sqrt(mean(f1)*m2[bid] + 1e-12) + f1 + f2   (fp16 output)
    enc_kernel<<<N_ / 4, 128>>>(bids);

    // glo = relu(glo - relu(t@Wg3 + bg3))   (fp16 in/out)
    gemm_kernel<AM_DENSE, EP_GLO><<<dim3(mt, 1), blk, GEMM_SMEM>>>(
        tb, nullptr, Wg3t, H_, H_, bg3, glo, glo, nullptr);

    // out = x + [convout | glo] @ W2 + b2   (fp32 output)
    gemm_kernel<AM_CONCAT, EP_FINAL><<<dim3(mt, 2), blk, GEMM_SMEM>>>(
        convout, glo, W2t, DIM_, 0, b2, x, out, nullptr);
}

// round 16
// speedup vs baseline: 2.3763x; 1.1337x over previous
#include <cuda_runtime.h>
#include <cuda_fp16.h>
#include <math.h>
#include <stdint.h>

// Problem constants (fixed shapes for GCM_60490319396973)
constexpr int N_   = 40000;
constexpr int DIM_ = 256;
constexpr int H_   = 128;
constexpr int K_   = 27;
constexpr int B_   = 4;
constexpr int KH_  = K_ * H_;      // 3456
constexpr int NPART = 250;
constexpr int CHUNK = (N_ + NPART - 1) / NPART;   // 160

// ---------------- scratch (device globals: no allocation allowed) ----------
__device__ __half g_convx[(N_ + 1) * H_];   // padded: row N_ is the zero row
__device__ __half g_glo  [(N_ + 1) * H_];
__device__ __half g_r1   [(N_ + 1) * H_];
__device__ __half g_convout[N_ * H_];
__device__ __half g_t    [N_ * H_];
__device__ __half g_xh   [N_ * DIM_];
__device__ float  g_f1[N_ * H_];
__device__ float  g_f2[N_ * H_];
__device__ float  g_part[NPART * B_ * H_];
__device__ int    g_cnt [NPART * B_];
__device__ float  g_m2  [B_ * H_];
// K-major (transposed) fp16 weights: [n][k]
__device__ __half g_W1t [DIM_ * DIM_];
__device__ __half g_W2t [DIM_ * DIM_];
__device__ __half g_Wg3t[H_ * H_];
__device__ __half g_Wr1t[H_ * KH_];
__device__ __half g_Wr2t[H_ * KH_];
__device__ __half g_Wg1t[H_ * KH_];
__device__ __half g_Wg2t[H_ * KH_];

// ---------------- helpers ----------------------------------------------------
__device__ __forceinline__ void mma_f16(float c[4], const uint32_t a[4],
                                        const uint32_t b[2]) {
    asm volatile(
        "mma.sync.aligned.m16n8k16.row.col.f32.f16.f16.f32 "
        "{%0,%1,%2,%3}, {%4,%5,%6,%7}, {%8,%9}, {%0,%1,%2,%3};\n"
        : "+f"(c[0]), "+f"(c[1]), "+f"(c[2]), "+f"(c[3])
        : "r"(a[0]), "r"(a[1]), "r"(a[2]), "r"(a[3]), "r"(b[0]), "r"(b[1]));
}
__device__ __forceinline__ void ldsm4(uint32_t& a, uint32_t& b,
                                      uint32_t& c, uint32_t& d, uint32_t addr) {
    asm volatile("ldmatrix.sync.aligned.m8n8.x4.shared.b16 {%0,%1,%2,%3}, [%4];"
                 : "=r"(a), "=r"(b), "=r"(c), "=r"(d) : "r"(addr));
}
__device__ __forceinline__ void cp16(uint32_t dst, const void* src, bool valid) {
    asm volatile("cp.async.cg.shared.global [%0], [%1], 16, %2;"
                 :: "r"(dst), "l"(src), "r"(valid ? 16 : 0));
}
__device__ __forceinline__ void cp16g(uint32_t dst, const void* src) {
    asm volatile("cp.async.cg.shared.global [%0], [%1], 16;"
                 :: "r"(dst), "l"(src));
}
__device__ __forceinline__ void cp_commit() {
    asm volatile("cp.async.commit_group;");
}
__device__ __forceinline__ void cp_wait0() {
    asm volatile("cp.async.wait_group 0;");
}

// ---------------- tiny kernels ---------------------------------------------
__global__ void zero_pad_kernel() {
    int t = threadIdx.x;                 // 128 threads
    g_convx[N_ * H_ + t] = __float2half(0.f);
    g_glo  [N_ * H_ + t] = __float2half(0.f);
    g_r1   [N_ * H_ + t] = __float2half(0.f);
}

// float -> half copy, 8 elements per thread
__global__ void f2h_kernel(const float* __restrict__ src,
                           __half* __restrict__ dst, int n8) {
    int i = blockIdx.x * blockDim.x + threadIdx.x;
    if (i >= n8) return;
    float4 v0 = reinterpret_cast<const float4*>(src)[i * 2];
    float4 v1 = reinterpret_cast<const float4*>(src)[i * 2 + 1];
    __half2* d = reinterpret_cast<__half2*>(dst) + i * 4;
    d[0] = __floats2half2_rn(v0.x, v0.y);
    d[1] = __floats2half2_rn(v0.z, v0.w);
    d[2] = __floats2half2_rn(v1.x, v1.y);
    d[3] = __floats2half2_rn(v1.z, v1.w);
}

// fused transpose of the 4 sconv weights: [KH_][H_] float -> [H_][KH_] half
__global__ void transpose4_h_kernel(const float* __restrict__ s0, __half* __restrict__ d0,
                                    const float* __restrict__ s1, __half* __restrict__ d1,
                                    const float* __restrict__ s2, __half* __restrict__ d2,
                                    const float* __restrict__ s3, __half* __restrict__ d3)
{
    __shared__ float t[32][33];
    const float* src; __half* dst;
    switch (blockIdx.z) {
        case 0: src = s0; dst = d0; break;
        case 1: src = s1; dst = d1; break;
        case 2: src = s2; dst = d2; break;
        default: src = s3; dst = d3; break;
    }
    int cb = blockIdx.x * 32;       // over H_
    int rb = blockIdx.y * 32;       // over KH_
    int x = threadIdx.x, y = threadIdx.y;
    for (int i = y; i < 32; i += 8)
        t[i][x] = src[(size_t)(rb + i) * H_ + cb + x];
    __syncthreads();
    for (int i = y; i < 32; i += 8)
        dst[(size_t)(cb + i) * KH_ + rb + x] = __float2half_rn(t[x][i]);
}

// fused transpose of W1, W2: [256][256] float -> [256][256] half K-major
__global__ void transpose2_h_kernel(const float* __restrict__ s0, __half* __restrict__ d0,
                                    const float* __restrict__ s1, __half* __restrict__ d1)
{
    __shared__ float t[32][33];
    const float* src = blockIdx.z ? s1 : s0;
    __half* dst      = blockIdx.z ? d1 : d0;
    int cb = blockIdx.x * 32;
    int rb = blockIdx.y * 32;
    int x = threadIdx.x, y = threadIdx.y;
    for (int i = y; i < 32; i += 8)
        t[i][x] = src[(size_t)(rb + i) * DIM_ + cb + x];
    __syncthreads();
    for (int i = y; i < 32; i += 8)
        dst[(size_t)(cb + i) * DIM_ + rb + x] = __float2half_rn(t[x][i]);
}

// [R][C] float -> [C][R] half transpose (generic, used for Wg3)
__global__ void transpose_h_kernel(const float* __restrict__ src,
                                   __half* __restrict__ dst, int R, int C) {
    __shared__ float t[32][33];
    int cb = blockIdx.x * 32;
    int rb = blockIdx.y * 32;
    int x = threadIdx.x, y = threadIdx.y;
    for (int i = y; i < 32; i += 8)
        t[i][x] = src[(size_t)(rb + i) * C + cb + x];
    __syncthreads();
    for (int i = y; i < 32; i += 8)
        dst[(size_t)(cb + i) * R + rb + x] = __float2half_rn(t[x][i]);
}

// ---------------- sconv: fp16 HMMA + ldmatrix, 128x64 tile per CTA ----------
// C[m, n0:n0+64] = epi( bias + sum_{k,c} A[nbr[m,k], c] * Wt[n, k*128+c] )
// gridDim = (313, 2, nz): y = N-half, z selects (B, bias, C) set (f1/f2 fusion)
enum { EPI_RELU = 0, EPI_R2 = 1 };

constexpr int SBK  = 64;                 // k per tile (halves)
constexpr int PAW  = 36;                 // A smem pitch in 32-bit words (72 halves)
constexpr int PBW  = 36;                 // B smem pitch in words
constexpr int SNT  = KH_ / SBK;          // 54
constexpr int ROWB = PAW * 4;            // 144 bytes per smem row
constexpr int SCONV_SMEM = (2 * 128 * PAW + 2 * 64 * PBW) * 4 + 128 * K_ * 4; // 69120

template <int EPI, int STOREH>
__global__ void __launch_bounds__(256, 3)
sconv_kernel(const __half* __restrict__ A,   // (N_+1) x 128 half, zero row N_
             const int* __restrict__ nbr,
             const __half* __restrict__ B0,  // [128][3456] half K-major
             const __half* __restrict__ B1,
             const float* __restrict__ bias0,
             const float* __restrict__ bias1,
             const __half* __restrict__ aux,
             void* __restrict__ C0v,
             void* __restrict__ C1v)
{
    extern __shared__ char smem_raw[];
    uint32_t* As32 = reinterpret_cast<uint32_t*>(smem_raw);        // [2][128][PAW]
    uint32_t* Bs32 = As32 + 2 * 128 * PAW;                         // [2][64][PBW]
    int*      snbr = reinterpret_cast<int*>(Bs32 + 2 * 64 * PBW);  // [128][27]

    const int z = blockIdx.z;
    const __half* Bm   = z ? B1 : B0;
    const float*  bias = z ? bias1 : bias0;
    void*         Cv   = z ? C1v : C0v;

    const int tid  = threadIdx.x;
    const int m0   = blockIdx.x * 128;
    const int n0   = blockIdx.y * 64;
    const int lane = tid & 31;
    const int wid  = tid >> 5;         // 0..7
    const int wm   = wid & 3;          // warp row (4 x 32 = 128)
    const int wn   = wid >> 2;         // warp col (2 x 32 = 64)
    const int g    = lane >> 2;        // 0..7
    const int tg   = lane & 3;         // 0..3

    // ldmatrix lane geometry
    const int lj = lane >> 3;          // 0..3
    const int rr = lane & 7;

    for (int i = tid; i < 128 * K_; i += 256) {
        int r = i / K_, k = i % K_;
        int row = m0 + r;
        snbr[i] = (row < N_) ? nbr[row * K_ + k] : N_;   // N_ -> zero row
    }
    __syncthreads();

    auto stage = [&](int t, int buf) {
        int k0   = t * SBK;
        int kidx = k0 >> 7;
        int csub = k0 & 127;           // 0 or 64
        uint32_t* Ab = As32 + buf * 128 * PAW;
        uint32_t* Bb = Bs32 + buf * 64 * PBW;
#pragma unroll
        for (int it = 0; it < 4; it++) {
            int idx = tid + it * 256;
            int r   = idx >> 3;            // 0..127
            int cu  = idx & 7;             // 16B chunk = 8 halves
            uint32_t dst = (uint32_t)__cvta_generic_to_shared(&Ab[r * PAW + cu * 4]);
            int src = snbr[r * K_ + kidx];
            cp16g(dst, A + (size_t)src * H_ + csub + cu * 8);
        }
#pragma unroll
        for (int it = 0; it < 2; it++) {
            int idx = tid + it * 256;
            int r   = idx >> 3;            // 0..63
            int cu  = idx & 7;
            uint32_t dst = (uint32_t)__cvta_generic_to_shared(&Bb[r * PBW + cu * 4]);
            cp16g(dst, Bm + (size_t)(n0 + r) * KH_ + k0 + cu * 8);
        }
    };

    float acc[2][4][4];
#pragma unroll
    for (int mt = 0; mt < 2; mt++)
#pragma unroll
        for (int nt = 0; nt < 4; nt++)
#pragma unroll
            for (int j = 0; j < 4; j++) acc[mt][nt][j] = 0.f;

    stage(0, 0);
    cp_commit();

    int buf = 0;
    for (int t = 0; t < SNT; t++) {
        cp_wait0();
        __syncthreads();
        if (t + 1 < SNT) { stage(t + 1, buf ^ 1); cp_commit(); }

        uint32_t aB = (uint32_t)__cvta_generic_to_shared(As32 + buf * 128 * PAW)
                    + (uint32_t)(wm * 32 + (lj & 1) * 8 + rr) * ROWB
                    + (uint32_t)((lj >> 1) * 8) * 2;
        uint32_t bB = (uint32_t)__cvta_generic_to_shared(Bs32 + buf * 64 * PBW)
                    + (uint32_t)(wn * 32 + (lj >> 1) * 8 + rr) * ROWB
                    + (uint32_t)((lj & 1) * 8) * 2;
#pragma unroll
        for (int kw = 0; kw < SBK / 2; kw += 8) {   // kw = k/2 word offset
            uint32_t kb = kw * 4;                    // byte offset
            uint32_t a0[4], a1[4];
            ldsm4(a0[0], a0[1], a0[2], a0[3], aB + kb);
            ldsm4(a1[0], a1[1], a1[2], a1[3], aB + 16 * ROWB + kb);
            uint32_t bv[8];
            ldsm4(bv[0], bv[1], bv[2], bv[3], bB + kb);              // nt 0,1
            ldsm4(bv[4], bv[5], bv[6], bv[7], bB + 16 * ROWB + kb);  // nt 2,3
#pragma unroll
            for (int nt = 0; nt < 4; nt++) {
                mma_f16(acc[0][nt], a0, bv + nt * 2);
                mma_f16(acc[1][nt], a1, bv + nt * 2);
            }
        }
        buf ^= 1;
    }

    // ---- epilogue ----
#pragma unroll
    for (int mt = 0; mt < 2; mt++) {
#pragma unroll
        for (int half = 0; half < 2; half++) {
            int row = m0 + wm * 32 + mt * 16 + g + half * 8;
            if (row >= N_) continue;
#pragma unroll
            for (int nt = 0; nt < 4; nt++) {
                int col = n0 + wn * 32 + nt * 8 + tg * 2;
                float v0 = acc[mt][nt][half * 2 + 0] + bias[col];
                float v1 = acc[mt][nt][half * 2 + 1] + bias[col + 1];
                float o0, o1;
                if (EPI == EPI_RELU) {
                    o0 = fmaxf(v0, 0.f);
                    o1 = fmaxf(v1, 0.f);
                } else {  // EPI_R2
                    float2 a = __half22float2(*reinterpret_cast<const __half2*>(
                        aux + (size_t)row * H_ + col));
                    o0 = fmaxf(v0, 0.f) + 2.f * a.x;
                    o1 = fmaxf(v1, 0.f) + 2.f * a.y;
                }
                if (STOREH) {
                    *reinterpret_cast<__half2*>(
                        reinterpret_cast<__half*>(Cv) + (size_t)row * H_ + col) =
                        __floats2half2_rn(o0, o1);
                } else {
                    *reinterpret_cast<float2*>(
                        reinterpret_cast<float*>(Cv) + (size_t)row * H_ + col) =
                        make_float2(o0, o1);
                }
            }
        }
    }
}

// ---------------- fp16 HMMA GEMM (dense / concat paths), 128x128 tile -------
enum { AM_DENSE = 0, AM_CONCAT = 2 };
enum { EP_SPLIT = 0, EP_GLO = 3, EP_FINAL = 4 };

constexpr int GEMM_SMEM = (2 * 128 * PAW + 2 * 128 * PBW) * 4;   // 73728

template <int AMODE, int EPI>
__global__ void __launch_bounds__(256, 2)
gemm_kernel(const __half* __restrict__ A, const __half* __restrict__ A2,
            const __half* __restrict__ Bt, int Kdim, int lda,
            const float* __restrict__ bias,
            const void* __restrict__ auxv,
            void* __restrict__ Cv, void* __restrict__ C2v)
{
    extern __shared__ char smem_raw[];
    uint32_t* As32 = reinterpret_cast<uint32_t*>(smem_raw);   // [2][128][PAW]
    uint32_t* Bs32 = As32 + 2 * 128 * PAW;                    // [2][128][PBW]

    const int tid = threadIdx.x;
    const int m0  = blockIdx.x * 128;
    const int n0  = blockIdx.y * 128;

    const int lane = tid & 31;
    const int wid  = tid >> 5;
    const int wm   = wid & 3;          // 4 x 32 = 128 rows
    const int wn   = wid >> 2;         // 2 x 64 = 128 cols
    const int g    = lane >> 2;
    const int tg   = lane & 3;
    const int lj   = lane >> 3;
    const int rr   = lane & 7;

    auto stage = [&](int k0, int buf) {
        uint32_t* Ab = As32 + buf * 128 * PAW;
        uint32_t* Bb = Bs32 + buf * 128 * PBW;
#pragma unroll
        for (int it = 0; it < 4; it++) {
            int idx = tid + it * 256;
            int r   = idx >> 3;
            int cu  = idx & 7;
            uint32_t dst = (uint32_t)__cvta_generic_to_shared(&Ab[r * PAW + cu * 4]);
            int row = m0 + r;
            if (AMODE == AM_DENSE) {
                cp16(dst, A + (size_t)row * lda + k0 + cu * 8, row < N_);
            } else {  // AM_CONCAT (k0 multiple of 64: chunk never straddles)
                int gc = k0 + cu * 8;
                const __half* srcp = (gc < H_) ? A : A2;
                int cc = (gc < H_) ? gc : gc - H_;
                cp16(dst, srcp + (size_t)row * H_ + cc, row < N_);
            }
        }
#pragma unroll
        for (int it = 0; it < 4; it++) {
            int idx = tid + it * 256;
            int r   = idx >> 3;
            int cu  = idx & 7;
            uint32_t dst = (uint32_t)__cvta_generic_to_shared(&Bb[r * PBW + cu * 4]);
            cp16g(dst, Bt + (size_t)(n0 + r) * Kdim + k0 + cu * 8);
        }
    };

    float acc[2][8][4];
#pragma unroll
    for (int mt = 0; mt < 2; mt++)
#pragma unroll
        for (int nt = 0; nt < 8; nt++)
#pragma unroll
            for (int j = 0; j < 4; j++) acc[mt][nt][j] = 0.f;

    const int niter = Kdim / SBK;
    stage(0, 0);
    cp_commit();

    int buf = 0;
    for (int i = 0; i < niter; i++) {
        cp_wait0();
        __syncthreads();
        if (i + 1 < niter) { stage((i + 1) * SBK, buf ^ 1); cp_commit(); }

        uint32_t aB = (uint32_t)__cvta_generic_to_shared(As32 + buf * 128 * PAW)
                    + (uint32_t)(wm * 32 + (lj & 1) * 8 + rr) * ROWB
                    + (uint32_t)((lj >> 1) * 8) * 2;
        uint32_t bB = (uint32_t)__cvta_generic_to_shared(Bs32 + buf * 128 * PBW)
                    + (uint32_t)(wn * 64 + (lj >> 1) * 8 + rr) * ROWB
                    + (uint32_t)((lj & 1) * 8) * 2;
#pragma unroll
        for (int kw = 0; kw < SBK / 2; kw += 8) {
            uint32_t kb = kw * 4;
            uint32_t a0[4], a1[4];
            ldsm4(a0[0], a0[1], a0[2], a0[3], aB + kb);
            ldsm4(a1[0], a1[1], a1[2], a1[3], aB + 16 * ROWB + kb);
            uint32_t bv[16];
#pragma unroll
            for (int p = 0; p < 4; p++)
                ldsm4(bv[p * 4 + 0], bv[p * 4 + 1], bv[p * 4 + 2], bv[p * 4 + 3],
                      bB + (uint32_t)p * 16 * ROWB + kb);
#pragma unroll
            for (int nt = 0; nt < 8; nt++) {
                mma_f16(acc[0][nt], a0, bv + nt * 2);
                mma_f16(acc[1][nt], a1, bv + nt * 2);
            }
        }
        buf ^= 1;
    }

#pragma unroll
    for (int mt = 0; mt < 2; mt++) {
#pragma unroll
        for (int half = 0; half < 2; half++) {
            int row = m0 + wm * 32 + mt * 16 + g + half * 8;
            if (row >= N_) continue;
#pragma unroll
            for (int nt = 0; nt < 8; nt++) {
                int col = n0 + wn * 64 + nt * 8 + tg * 2;
                float v0 = acc[mt][nt][half * 2 + 0] + bias[col];
                float v1 = acc[mt][nt][half * 2 + 1] + bias[col + 1];
                if (EPI == EP_SPLIT) {
                    __half2 o = __floats2half2_rn(v0, v1);
                    if (col < H_)
                        *reinterpret_cast<__half2*>(
                            reinterpret_cast<__half*>(Cv) + (size_t)row * H_ + col) = o;
                    else
                        *reinterpret_cast<__half2*>(
                            reinterpret_cast<__half*>(C2v) + (size_t)row * H_ + col - H_) = o;
                } else if (EPI == EP_GLO) {
                    float2 a = __half22float2(*reinterpret_cast<const __half2*>(
                        reinterpret_cast<const __half*>(auxv) + (size_t)row * H_ + col));
                    float o0 = fmaxf(a.x - fmaxf(v0, 0.f), 0.f);
                    float o1 = fmaxf(a.y - fmaxf(v1, 0.f), 0.f);
                    *reinterpret_cast<__half2*>(
                        reinterpret_cast<__half*>(Cv) + (size_t)row * H_ + col) =
                        __floats2half2_rn(o0, o1);
                } else {  // EP_FINAL
                    float2 a = *reinterpret_cast<const float2*>(
                        reinterpret_cast<const float*>(auxv) + (size_t)row * DIM_ + col);
                    *reinterpret_cast<float2*>(
                        reinterpret_cast<float*>(Cv) + (size_t)row * DIM_ + col) =
                        make_float2(a.x + v0, a.y + v1);
                }
            }
        }
    }
}

// ---------------- deterministic segment mean (m2) ---------------------------
__global__ void seg_partial_kernel(const int* __restrict__ bids) {
    int blk = blockIdx.x;
    int o   = threadIdx.x;
    int r0  = blk * CHUNK;
    int r1  = min(r0 + CHUNK, N_);
    float a0 = 0.f, a1 = 0.f, a2 = 0.f, a3 = 0.f;
    for (int r = r0; r < r1; r++) {
        int   b = bids[r];
        float v = g_f2[(size_t)r * H_ + o];
        a0 += (b == 0) ? v : 0.f;
        a1 += (b == 1) ? v : 0.f;
        a2 += (b == 2) ? v : 0.f;
        a3 += (b == 3) ? v : 0.f;
    }
    g_part[(blk * B_ + 0) * H_ + o] = a0;
    g_part[(blk * B_ + 1) * H_ + o] = a1;
    g_part[(blk * B_ + 2) * H_ + o] = a2;
    g_part[(blk * B_ + 3) * H_ + o] = a3;
    if (o < B_) {
        int c = 0;
        for (int r = r0; r < r1; r++) c += (bids[r] == o);
        g_cnt[blk * B_ + o] = c;
    }
}

__global__ void seg_final_kernel() {
    int t = threadIdx.x;
    float s = 0.f;
    for (int p = 0; p < NPART; p++) s += g_part[p * B_ * H_ + t];
    __shared__ int scnt[B_];
    if (t < B_) {
        int c = 0;
        for (int p = 0; p < NPART; p++) c += g_cnt[p * B_ + t];
        scnt[t] = c;
    }
    __syncthreads();
    int b = t / H_;
    float cnt = (float)max(scnt[b], 1);
    g_m2[t] = s / cnt;
}

// ---------------- enc / t = enc + f1 + f2 (stores fp16) ---------------------
__global__ void enc_kernel(const int* __restrict__ bids) {
    int warp = threadIdx.x >> 5;
    int lane = threadIdx.x & 31;
    int row  = blockIdx.x * 4 + warp;

    float4 f1v = reinterpret_cast<const float4*>(g_f1 + (size_t)row * H_)[lane];
    float s = f1v.x + f1v.y + f1v.z + f1v.w;
#pragma unroll
    for (int off = 16; off; off >>= 1) s += __shfl_xor_sync(0xffffffffu, s, off);
    float row1 = s * (1.f / 128.f);

    int b = bids[row];
    float4 f2v = reinterpret_cast<const float4*>(g_f2 + (size_t)row * H_)[lane];
    float4 m2v = reinterpret_cast<const float4*>(g_m2 + b * H_)[lane];

    float t0 = sqrtf(row1 * m2v.x + 1e-12f) + f1v.x + f2v.x;
    float t1 = sqrtf(row1 * m2v.y + 1e-12f) + f1v.y + f2v.y;
    float t2 = sqrtf(row1 * m2v.z + 1e-12f) + f1v.z + f2v.z;
    float t3 = sqrtf(row1 * m2v.w + 1e-12f) + f1v.w + f2v.w;
    __half2* dst = reinterpret_cast<__half2*>(g_t + (size_t)row * H_);
    dst[lane * 2 + 0] = __floats2half2_rn(t0, t1);
    dst[lane * 2 + 1] = __floats2half2_rn(t2, t3);
}

// ---------------- launch ----------------------------------------------------
extern "C" void kernel_launch(void* const* d_in, const int* in_sizes, int n_in,
                              void* d_out, int out_size)
{
    const float* x    = (const float*)d_in[0];
    const int*   nbr  = (const int*)  d_in[1];
    const int*   bids = (const int*)  d_in[2];
    const float* W1   = (const float*)d_in[3];
    const float* b1   = (const float*)d_in[4];
    const float* W2   = (const float*)d_in[5];
    const float* b2   = (const float*)d_in[6];
    const float* Wr1  = (const float*)d_in[7];
    const float* br1  = (const float*)d_in[8];
    const float* Wr2  = (const float*)d_in[9];
    const float* br2  = (const float*)d_in[10];
    const float* Wg1  = (const float*)d_in[11];
    const float* bg1  = (const float*)d_in[12];
    const float* Wg2  = (const float*)d_in[13];
    const float* bg2  = (const float*)d_in[14];
    const float* Wg3  = (const float*)d_in[15];
    const float* bg3  = (const float*)d_in[16];
    float* out = (float*)d_out;

    __half *convx, *glo, *r1, *convout, *tb, *xh;
    __half *W1t, *W2t, *Wg3t, *Wr1t, *Wr2t, *Wg1t, *Wg2t;
    float *f1, *f2;
    cudaGetSymbolAddress((void**)&convx,   g_convx);
    cudaGetSymbolAddress((void**)&glo,     g_glo);
    cudaGetSymbolAddress((void**)&r1,      g_r1);
    cudaGetSymbolAddress((void**)&convout, g_convout);
    cudaGetSymbolAddress((void**)&tb,      g_t);
    cudaGetSymbolAddress((void**)&xh,      g_xh);
    cudaGetSymbolAddress((void**)&f1,      g_f1);
    cudaGetSymbolAddress((void**)&f2,      g_f2);
    cudaGetSymbolAddress((void**)&W1t,     g_W1t);
    cudaGetSymbolAddress((void**)&W2t,     g_W2t);
    cudaGetSymbolAddress((void**)&Wg3t,    g_Wg3t);
    cudaGetSymbolAddress((void**)&Wr1t,    g_Wr1t);
    cudaGetSymbolAddress((void**)&Wr2t,    g_Wr2t);
    cudaGetSymbolAddress((void**)&Wg1t,    g_Wg1t);
    cudaGetSymbolAddress((void**)&Wg2t,    g_Wg2t);

    cudaFuncSetAttribute(gemm_kernel<AM_DENSE,  EP_SPLIT>,
                         cudaFuncAttributeMaxDynamicSharedMemorySize, GEMM_SMEM);
    cudaFuncSetAttribute(gemm_kernel<AM_DENSE,  EP_GLO>,
                         cudaFuncAttributeMaxDynamicSharedMemorySize, GEMM_SMEM);
    cudaFuncSetAttribute(gemm_kernel<AM_CONCAT, EP_FINAL>,
                         cudaFuncAttributeMaxDynamicSharedMemorySize, GEMM_SMEM);
    cudaFuncSetAttribute(sconv_kernel<EPI_RELU, 1>,
                         cudaFuncAttributeMaxDynamicSharedMemorySize, SCONV_SMEM);
    cudaFuncSetAttribute(sconv_kernel<EPI_RELU, 0>,
                         cudaFuncAttributeMaxDynamicSharedMemorySize, SCONV_SMEM);
    cudaFuncSetAttribute(sconv_kernel<EPI_R2,   1>,
                         cudaFuncAttributeMaxDynamicSharedMemorySize, SCONV_SMEM);

    const int mt = (N_ + 127) / 128;   // 313
    dim3 blk(256);

    // ---- prep: fp16 copies / K-major transposes (fused launches) ----
    {
        int n8 = (N_ * DIM_) / 8;
        f2h_kernel<<<(n8 + 255) / 256, 256>>>(x, xh, n8);
    }
    transpose2_h_kernel<<<dim3(DIM_ / 32, DIM_ / 32, 2), dim3(32, 8)>>>(
        W1, W1t, W2, W2t);
    transpose_h_kernel<<<dim3(H_ / 32, H_ / 32), dim3(32, 8)>>>(Wg3, Wg3t, H_, H_);
    transpose4_h_kernel<<<dim3(H_ / 32, KH_ / 32, 4), dim3(32, 8)>>>(
        Wr1, Wr1t, Wr2, Wr2t, Wg1, Wg1t, Wg2, Wg2t);
    zero_pad_kernel<<<1, 128>>>();

    // h = x@W1 + b1 ; conv_x = h[:, :128] ; glo = h[:, 128:]  (fp16 outputs)
    gemm_kernel<AM_DENSE, EP_SPLIT><<<dim3(mt, 2), blk, GEMM_SMEM>>>(
        xh, nullptr, W1t, DIM_, DIM_, b1, nullptr, convx, glo);

    // r1 = relu(sconv(conv_x, Wr1, br1))
    sconv_kernel<EPI_RELU, 1><<<dim3(mt, 2, 1), blk, SCONV_SMEM>>>(
        convx, nbr, Wr1t, Wr1t, br1, br1, nullptr, r1, r1);

    // convout = relu(sconv(r1, Wr2, br2)) + 2*conv_x
    sconv_kernel<EPI_R2, 1><<<dim3(mt, 2, 1), blk, SCONV_SMEM>>>(
        r1, nbr, Wr2t, Wr2t, br2, br2, convx, convout, convout);

    // f1 / f2 fused in one launch (fp32 outputs for exact seg/enc path)
    sconv_kernel<EPI_RELU, 0><<<dim3(mt, 2, 2), blk, SCONV_SMEM>>>(
        glo, nbr, Wg1t, Wg2t, bg1, bg2, nullptr, f1, f2);

    // m2 = segment_mean(f2) (deterministic two-pass)
    seg_partial_kernel<<<NPART, 128>>>(bids);
    seg_final_kernel<<<1, 512>>>();

    // t = sqrt(mean(f1)*m2[bid] + 1e-12) + f1 + f2   (fp16 output)
    enc_kernel<<<N_ / 4, 128>>>(bids);

    // glo = relu(glo - relu(t@Wg3 + bg3))   (fp16 in/out)
    gemm_kernel<AM_DENSE, EP_GLO><<<dim3(mt, 1), blk, GEMM_SMEM>>>(
        tb, nullptr, Wg3t, H_, H_, bg3, glo, glo, nullptr);

    // out = x + [convout | glo] @ W2 + b2   (fp32 output)
    gemm_kernel<AM_CONCAT, EP_FINAL><<<dim3(mt, 2), blk, GEMM_SMEM>>>(
        convout, glo, W2t, DIM_, 0, b2, x, out, nullptr);
}